// round 8
// baseline (speedup 1.0000x reference)
#include <cuda_runtime.h>
#include <cuda_bf16.h>
#include <stdint.h>

// GCN_57501022159512: 2-layer GCN, N=100000 nodes, E=1600000 edges, 64 -> 128 -> 128.
// h1 = relu(gcnconv(x, W1, b1)); t = batchnorm(h1); out = relu(gcnconv(t, W2, b2))
//
// R8: GEMM inner loops converted to packed fma.rn.f32x2 (FFMA2): weights kept
// as packed (k even, k odd) u64 register pairs, su rows consumed as ulonglong2
// (LDS.128 -> 2 packed operands), 2 independent accumulator pairs.
// ~1.6x fewer issue slots per MAC in the FFMA-bound GEMMs.

#define NNODES 100000
#define NEDGES 1600000
#define FIN    64
#define FHID   128
#define BN_EPS 1e-5f

#define NB_SCAN 100
#define NODES_PER_BLK 1000   // NNODES / NB_SCAN, exact

// ---------------- scratch (device globals; no allocs allowed) ----------------
__device__ float g_h1[NNODES * FHID];    // x @ W1
__device__ float g_t [NNODES * FHID];    // relu/bn input (gather1 output)
__device__ float g_h2[NNODES * FHID];    // bn(t) @ W2
__device__ float g_dinv[NNODES];
__device__ int   g_deg [NNODES];
__device__ float g_stats[2 * FHID];      // sum,sumsq -> then scale,shift
__device__ int   g_eidx[2 * NEDGES];     // decoded int32 edge index [row | col]
__device__ int   g_off [NNODES + 1];     // CSR offsets (by destination col)
__device__ int   g_cursor[NNODES];       // placement cursors
__device__ int2  g_csr[NEDGES];          // (src row, norm bits) sorted by dest
__device__ int   g_bsum[NB_SCAN];        // per-block degree sums
__device__ int   g_is64;

// ---------------- f32x2 helpers ----------------
__device__ __forceinline__ void fma2(unsigned long long& d,
                                     unsigned long long a,
                                     unsigned long long b) {
    asm("fma.rn.f32x2 %0, %1, %2, %0;" : "+l"(d) : "l"(a), "l"(b));
}
__device__ __forceinline__ unsigned long long pack2(float lo, float hi) {
    unsigned long long r;
    asm("mov.b64 %0, {%1, %2};" : "=l"(r) : "f"(lo), "f"(hi));
    return r;
}
__device__ __forceinline__ float hsum2(unsigned long long v) {
    float lo, hi;
    asm("mov.b64 {%0, %1}, %2;" : "=f"(lo), "=f"(hi) : "l"(v));
    return lo + hi;
}

// ---------------- small setup kernels ----------------

__global__ void k_zero() {
    const int idx = blockIdx.x * blockDim.x + threadIdx.x;
    const int stride = gridDim.x * blockDim.x;
    for (int j = idx; j < NNODES; j += stride) g_deg[j] = 0;
    if (idx < 2 * FHID) g_stats[idx] = 0.f;
}

// Detect whether the edge_index buffer is int64 or int32.
__global__ void k_detect(const int* __restrict__ w) {
    __shared__ int bad;
    if (threadIdx.x == 0) bad = 0;
    __syncthreads();
    for (int j = threadIdx.x; j < 1024; j += blockDim.x) {
        const int lo = w[2 * j], hi = w[2 * j + 1];
        if (hi != 0 || lo < 0 || lo >= NNODES) bad = 1;
    }
    __syncthreads();
    if (threadIdx.x == 0) g_is64 = (bad == 0) ? 1 : 0;
}

// Decode edge indices into int32 scratch (clamped) + degree count on col.
__global__ void k_decode(const void* __restrict__ ei) {
    const int idx = blockIdx.x * blockDim.x + threadIdx.x;
    const int stride = gridDim.x * blockDim.x;
    const bool is64 = (g_is64 != 0);
    const long long* e64 = (const long long*)ei;
    const int*       e32 = (const int*)ei;
    for (int e = idx; e < 2 * NEDGES; e += stride) {
        int v = is64 ? (int)e64[e] : e32[e];
        v = min(max(v, 0), NNODES - 1);
        g_eidx[e] = v;
        if (e >= NEDGES) atomicAdd(&g_deg[v], 1);   // col half -> degree
    }
}

// Stage A: per-block degree sums. Block b covers nodes [b*1000, (b+1)*1000).
__global__ void k_scanA() {
    __shared__ int red[256];
    const int b = blockIdx.x;
    const int t = threadIdx.x;
    const int beg = b * NODES_PER_BLK;
    int s = 0;
    for (int i = t; i < NODES_PER_BLK; i += 256) s += g_deg[beg + i];
    red[t] = s;
    __syncthreads();
    for (int d = 128; d > 0; d >>= 1) {
        if (t < d) red[t] += red[t + d];
        __syncthreads();
    }
    if (t == 0) g_bsum[b] = red[0];
}

// Stage C: block b computes its base, scans its 1000 nodes, writes offsets,
// cursors and dinv (fused).
__global__ void k_scanC() {
    __shared__ int red[256];
    __shared__ int partial[256];
    __shared__ int s_base;
    const int b = blockIdx.x;
    const int t = threadIdx.x;
    const int beg = b * NODES_PER_BLK;

    int s = (t < b) ? g_bsum[t] : 0;
    red[t] = s;
    __syncthreads();
    for (int d = 128; d > 0; d >>= 1) {
        if (t < d) red[t] += red[t + d];
        __syncthreads();
    }
    if (t == 0) s_base = red[0];
    __syncthreads();

    const int cbeg = t * 4;
    int csum = 0;
    int dloc[4];
#pragma unroll
    for (int j = 0; j < 4; j++) {
        const int i = cbeg + j;
        dloc[j] = (i < NODES_PER_BLK) ? g_deg[beg + i] : 0;
        csum += dloc[j];
    }
    partial[t] = csum;
    __syncthreads();
    for (int d = 1; d < 256; d <<= 1) {
        int v = (t >= d) ? partial[t - d] : 0;
        __syncthreads();
        partial[t] += v;
        __syncthreads();
    }
    int run = s_base + ((t == 0) ? 0 : partial[t - 1]);
#pragma unroll
    for (int j = 0; j < 4; j++) {
        const int i = cbeg + j;
        if (i < NODES_PER_BLK) {
            g_off[beg + i] = run;
            g_cursor[beg + i] = run;
            g_dinv[beg + i] = rsqrtf((float)(dloc[j] + 1));
            run += dloc[j];
        }
    }
    if (b == NB_SCAN - 1 && t == 255) g_off[NNODES] = run;
}

// Counting sort: place (row, norm) records into destination-sorted CSR array.
__global__ void k_fillcsr() {
    const int idx = blockIdx.x * blockDim.x + threadIdx.x;
    const int stride = gridDim.x * blockDim.x;
    for (int e = idx; e < NEDGES; e += stride) {
        const int r = g_eidx[e];
        const int c = g_eidx[NEDGES + e];
        const int pos = atomicAdd(&g_cursor[c], 1);
        const float nm = g_dinv[r] * g_dinv[c];
        g_csr[pos] = make_int2(r, __float_as_int(nm));
    }
}

// ---------------- GEMMs (packed f32x2) ----------------

// h1 = x @ W1. Thread f keeps W1[:,f] as 32 packed (even,odd) pairs.
__global__ void __launch_bounds__(FHID, 4) k_gemm1(const float* __restrict__ x,
                                                   const float* __restrict__ W1) {
    __shared__ __align__(16) float sx[4][FIN];
    const int f = threadIdx.x;
    unsigned long long wp[FIN / 2];
#pragma unroll
    for (int k = 0; k < FIN / 2; k++)
        wp[k] = pack2(W1[(2 * k) * FHID + f], W1[(2 * k + 1) * FHID + f]);

    for (int base = blockIdx.x * 4; base < NNODES; base += gridDim.x * 4) {
        for (int i = threadIdx.x; i < 4 * FIN; i += FHID)
            sx[i >> 6][i & 63] = x[(size_t)base * FIN + i];
        __syncthreads();
#pragma unroll
        for (int j = 0; j < 4; j++) {
            const ulonglong2* s2 = reinterpret_cast<const ulonglong2*>(sx[j]);
            unsigned long long acc0 = 0ull, acc1 = 0ull;
#pragma unroll
            for (int k = 0; k < FIN / 4; k++) {        // 16 iters, 4 floats each
                const ulonglong2 a = s2[k];
                fma2(acc0, a.x, wp[2 * k]);
                fma2(acc1, a.y, wp[2 * k + 1]);
            }
            g_h1[(size_t)(base + j) * FHID + f] = hsum2(acc0) + hsum2(acc1);
        }
        __syncthreads();
    }
}

// h2 = bn(t) @ W2. Thread f keeps W2[:,f] as 64 packed pairs; BN on row load.
__global__ void __launch_bounds__(FHID, 2) k_gemm2(const float* __restrict__ W2) {
    __shared__ __align__(16) float su[2][FHID];
    const int f = threadIdx.x;
    unsigned long long wp[FHID / 2];
#pragma unroll
    for (int k = 0; k < FHID / 2; k++)
        wp[k] = pack2(W2[(2 * k) * FHID + f], W2[(2 * k + 1) * FHID + f]);
    const float scale = g_stats[f];
    const float shift = g_stats[FHID + f];

    for (int base = blockIdx.x * 2; base < NNODES; base += gridDim.x * 2) {
        su[0][f] = fmaf(g_t[(size_t)base * FHID + f], scale, shift);
        su[1][f] = fmaf(g_t[(size_t)(base + 1) * FHID + f], scale, shift);
        __syncthreads();
#pragma unroll
        for (int j = 0; j < 2; j++) {
            const ulonglong2* s2 = reinterpret_cast<const ulonglong2*>(su[j]);
            unsigned long long acc0 = 0ull, acc1 = 0ull;
#pragma unroll
            for (int k = 0; k < FHID / 4; k++) {       // 32 iters, 4 floats each
                const ulonglong2 a = s2[k];
                fma2(acc0, a.x, wp[2 * k]);
                fma2(acc1, a.y, wp[2 * k + 1]);
            }
            g_h2[(size_t)(base + j) * FHID + f] = hsum2(acc0) + hsum2(acc1);
        }
        __syncthreads();
    }
}

// ---------------- gathers (warp per destination node) ----------------

// t[c] = relu( sum_{e->c} h1[r]*norm + h1[c]*dinv[c]^2 + b1 ); BN partial sums.
__global__ void k_gather1(const float* __restrict__ b1) {
    const int lane = threadIdx.x & 31;                 // feature quad
    const int warp = (blockIdx.x * blockDim.x + threadIdx.x) >> 5;
    const int nwarps = (gridDim.x * blockDim.x) >> 5;
    const float4 bf = reinterpret_cast<const float4*>(b1)[lane];
    const float4* h4 = reinterpret_cast<const float4*>(g_h1);
    float4* t4 = reinterpret_cast<float4*>(g_t);
    float4 s  = make_float4(0.f, 0.f, 0.f, 0.f);
    float4 ss = make_float4(0.f, 0.f, 0.f, 0.f);

    for (int c = warp; c < NNODES; c += nwarps) {
        const int beg = g_off[c], end = g_off[c + 1];
        const float dc = g_dinv[c];
        const float d2 = dc * dc;
        float4 h = h4[(size_t)c * 32 + lane];
        float4 acc = make_float4(h.x * d2, h.y * d2, h.z * d2, h.w * d2);
        for (int i = beg; i < end; i++) {
            const int2 en = g_csr[i];
            const float nm = __int_as_float(en.y);
            const float4 v = h4[(size_t)en.x * 32 + lane];
            acc.x = fmaf(v.x, nm, acc.x);
            acc.y = fmaf(v.y, nm, acc.y);
            acc.z = fmaf(v.z, nm, acc.z);
            acc.w = fmaf(v.w, nm, acc.w);
        }
        acc.x = fmaxf(acc.x + bf.x, 0.f);
        acc.y = fmaxf(acc.y + bf.y, 0.f);
        acc.z = fmaxf(acc.z + bf.z, 0.f);
        acc.w = fmaxf(acc.w + bf.w, 0.f);
        t4[(size_t)c * 32 + lane] = acc;
        s.x += acc.x; s.y += acc.y; s.z += acc.z; s.w += acc.w;
        ss.x += acc.x * acc.x; ss.y += acc.y * acc.y;
        ss.z += acc.z * acc.z; ss.w += acc.w * acc.w;
    }
    float* st = &g_stats[4 * lane];
    atomicAdd(st + 0, s.x); atomicAdd(st + 1, s.y);
    atomicAdd(st + 2, s.z); atomicAdd(st + 3, s.w);
    st = &g_stats[FHID + 4 * lane];
    atomicAdd(st + 0, ss.x); atomicAdd(st + 1, ss.y);
    atomicAdd(st + 2, ss.z); atomicAdd(st + 3, ss.w);
}

// out[c] = relu( sum_{e->c} h2[r]*norm + h2[c]*dinv[c]^2 + b2 )
__global__ void k_gather2(float* __restrict__ out, const float* __restrict__ b2) {
    const int lane = threadIdx.x & 31;
    const int warp = (blockIdx.x * blockDim.x + threadIdx.x) >> 5;
    const int nwarps = (gridDim.x * blockDim.x) >> 5;
    const float4 bf = reinterpret_cast<const float4*>(b2)[lane];
    const float4* h4 = reinterpret_cast<const float4*>(g_h2);
    float4* o4 = reinterpret_cast<float4*>(out);

    for (int c = warp; c < NNODES; c += nwarps) {
        const int beg = g_off[c], end = g_off[c + 1];
        const float dc = g_dinv[c];
        const float d2 = dc * dc;
        float4 h = h4[(size_t)c * 32 + lane];
        float4 acc = make_float4(h.x * d2, h.y * d2, h.z * d2, h.w * d2);
        for (int i = beg; i < end; i++) {
            const int2 en = g_csr[i];
            const float nm = __int_as_float(en.y);
            const float4 v = h4[(size_t)en.x * 32 + lane];
            acc.x = fmaf(v.x, nm, acc.x);
            acc.y = fmaf(v.y, nm, acc.y);
            acc.z = fmaf(v.z, nm, acc.z);
            acc.w = fmaf(v.w, nm, acc.w);
        }
        acc.x = fmaxf(acc.x + bf.x, 0.f);
        acc.y = fmaxf(acc.y + bf.y, 0.f);
        acc.z = fmaxf(acc.z + bf.z, 0.f);
        acc.w = fmaxf(acc.w + bf.w, 0.f);
        o4[(size_t)c * 32 + lane] = acc;
    }
}

// fold BN into per-feature scale/shift
__global__ void k_bnfold(const float* __restrict__ gamma, const float* __restrict__ beta) {
    const int f = threadIdx.x;
    const float inv_n = 1.0f / (float)NNODES;
    const float mean = g_stats[f] * inv_n;
    const float var  = g_stats[FHID + f] * inv_n - mean * mean;
    const float rstd = rsqrtf(var + BN_EPS);
    const float scale = gamma[f] * rstd;
    g_stats[f]        = scale;
    g_stats[FHID + f] = beta[f] - mean * scale;
}

// ---------------- launch ----------------
extern "C" void kernel_launch(void* const* d_in, const int* in_sizes, int n_in,
                              void* d_out, int out_size) {
    const float* x     = (const float*)d_in[0];
    const void*  ei    = d_in[1];                 // [2, E], int32 OR int64 (detected)
    const float* W1    = (const float*)d_in[2];
    const float* b1    = (const float*)d_in[3];
    const float* gamma = (const float*)d_in[4];
    const float* beta  = (const float*)d_in[5];
    const float* W2    = (const float*)d_in[6];
    const float* b2    = (const float*)d_in[7];
    float* out = (float*)d_out;

    k_zero<<<512, 256>>>();
    k_detect<<<1, 256>>>((const int*)ei);
    k_decode<<<2048, 256>>>(ei);
    k_scanA<<<NB_SCAN, 256>>>();
    k_scanC<<<NB_SCAN, 256>>>();
    k_fillcsr<<<2048, 256>>>();

    k_gemm1<<<888, FHID>>>(x, W1);
    k_gather1<<<1184, 256>>>(b1);
    k_bnfold<<<1, FHID>>>(gamma, beta);

    k_gemm2<<<592, FHID>>>(W2);
    k_gather2<<<1184, 256>>>(out, b2);
}

// round 9
// speedup vs baseline: 1.0267x; 1.0267x over previous
#include <cuda_runtime.h>
#include <cuda_bf16.h>
#include <stdint.h>

// GCN_57501022159512: 2-layer GCN, N=100000 nodes, E=1600000 edges, 64 -> 128 -> 128.
// h1 = relu(gcnconv(x, W1, b1)); t = batchnorm(h1); out = relu(gcnconv(t, W2, b2))
//
// R9: revert R8's f32x2 GEMMs (regressed; loops weren't FFMA-issue bound) back
// to R7 scalar FFMA form, and eliminate the g_eidx staging array: k_deg and
// k_fillcsr read the edge_index buffer directly (dtype-aware). One fewer
// 25.6MB-traffic kernel in the CSR build chain.

#define NNODES 100000
#define NEDGES 1600000
#define FIN    64
#define FHID   128
#define BN_EPS 1e-5f

#define NB_SCAN 100
#define NODES_PER_BLK 1000   // NNODES / NB_SCAN, exact

// ---------------- scratch (device globals; no allocs allowed) ----------------
__device__ float g_h1[NNODES * FHID];    // x @ W1
__device__ float g_t [NNODES * FHID];    // relu/bn input (gather1 output)
__device__ float g_h2[NNODES * FHID];    // bn(t) @ W2
__device__ float g_dinv[NNODES];
__device__ int   g_deg [NNODES];
__device__ float g_stats[2 * FHID];      // sum,sumsq -> then scale,shift
__device__ int   g_off [NNODES + 1];     // CSR offsets (by destination col)
__device__ int   g_cursor[NNODES];       // placement cursors
__device__ int2  g_csr[NEDGES];          // (src row, norm bits) sorted by dest
__device__ int   g_bsum[NB_SCAN];        // per-block degree sums
__device__ int   g_is64;

// ---------------- small setup kernels ----------------

__global__ void k_zero() {
    const int idx = blockIdx.x * blockDim.x + threadIdx.x;
    const int stride = gridDim.x * blockDim.x;
    for (int j = idx; j < NNODES; j += stride) g_deg[j] = 0;
    if (idx < 2 * FHID) g_stats[idx] = 0.f;
}

// Detect whether the edge_index buffer is int64 or int32.
__global__ void k_detect(const int* __restrict__ w) {
    __shared__ int bad;
    if (threadIdx.x == 0) bad = 0;
    __syncthreads();
    for (int j = threadIdx.x; j < 1024; j += blockDim.x) {
        const int lo = w[2 * j], hi = w[2 * j + 1];
        if (hi != 0 || lo < 0 || lo >= NNODES) bad = 1;
    }
    __syncthreads();
    if (threadIdx.x == 0) g_is64 = (bad == 0) ? 1 : 0;
}

__device__ __forceinline__ int load_idx(const void* ei, int pos, bool is64) {
    int v = is64 ? (int)((const long long*)ei)[pos] : ((const int*)ei)[pos];
    return min(max(v, 0), NNODES - 1);
}

// Degree count directly from edge buffer (col half).
__global__ void k_deg(const void* __restrict__ ei) {
    const int idx = blockIdx.x * blockDim.x + threadIdx.x;
    const int stride = gridDim.x * blockDim.x;
    const bool is64 = (g_is64 != 0);
    for (int e = idx; e < NEDGES; e += stride)
        atomicAdd(&g_deg[load_idx(ei, NEDGES + e, is64)], 1);
}

// Stage A: per-block degree sums. Block b covers nodes [b*1000, (b+1)*1000).
__global__ void k_scanA() {
    __shared__ int red[256];
    const int b = blockIdx.x;
    const int t = threadIdx.x;
    const int beg = b * NODES_PER_BLK;
    int s = 0;
    for (int i = t; i < NODES_PER_BLK; i += 256) s += g_deg[beg + i];
    red[t] = s;
    __syncthreads();
    for (int d = 128; d > 0; d >>= 1) {
        if (t < d) red[t] += red[t + d];
        __syncthreads();
    }
    if (t == 0) g_bsum[b] = red[0];
}

// Stage C: block b computes its base, scans its 1000 nodes, writes offsets,
// cursors and dinv (fused).
__global__ void k_scanC() {
    __shared__ int red[256];
    __shared__ int partial[256];
    __shared__ int s_base;
    const int b = blockIdx.x;
    const int t = threadIdx.x;
    const int beg = b * NODES_PER_BLK;

    int s = (t < b) ? g_bsum[t] : 0;
    red[t] = s;
    __syncthreads();
    for (int d = 128; d > 0; d >>= 1) {
        if (t < d) red[t] += red[t + d];
        __syncthreads();
    }
    if (t == 0) s_base = red[0];
    __syncthreads();

    const int cbeg = t * 4;
    int csum = 0;
    int dloc[4];
#pragma unroll
    for (int j = 0; j < 4; j++) {
        const int i = cbeg + j;
        dloc[j] = (i < NODES_PER_BLK) ? g_deg[beg + i] : 0;
        csum += dloc[j];
    }
    partial[t] = csum;
    __syncthreads();
    for (int d = 1; d < 256; d <<= 1) {
        int v = (t >= d) ? partial[t - d] : 0;
        __syncthreads();
        partial[t] += v;
        __syncthreads();
    }
    int run = s_base + ((t == 0) ? 0 : partial[t - 1]);
#pragma unroll
    for (int j = 0; j < 4; j++) {
        const int i = cbeg + j;
        if (i < NODES_PER_BLK) {
            g_off[beg + i] = run;
            g_cursor[beg + i] = run;
            g_dinv[beg + i] = rsqrtf((float)(dloc[j] + 1));
            run += dloc[j];
        }
    }
    if (b == NB_SCAN - 1 && t == 255) g_off[NNODES] = run;
}

// Counting sort directly from edge buffer: place (row, norm) records into
// destination-sorted CSR array.
__global__ void k_fillcsr(const void* __restrict__ ei) {
    const int idx = blockIdx.x * blockDim.x + threadIdx.x;
    const int stride = gridDim.x * blockDim.x;
    const bool is64 = (g_is64 != 0);
    for (int e = idx; e < NEDGES; e += stride) {
        const int r = load_idx(ei, e, is64);
        const int c = load_idx(ei, NEDGES + e, is64);
        const int pos = atomicAdd(&g_cursor[c], 1);
        const float nm = g_dinv[r] * g_dinv[c];
        g_csr[pos] = make_int2(r, __float_as_int(nm));
    }
}

// ---------------- GEMMs (scalar FFMA, R7 form) ----------------

// h1 = x @ W1.  128 threads/block; thread f keeps W1[:,f] (64 vals) in regs.
__global__ void k_gemm1(const float* __restrict__ x, const float* __restrict__ W1) {
    __shared__ float sx[4][FIN];
    const int f = threadIdx.x;
    float w[FIN];
#pragma unroll
    for (int k = 0; k < FIN; k++) w[k] = W1[k * FHID + f];

    for (int base = blockIdx.x * 4; base < NNODES; base += gridDim.x * 4) {
        for (int i = threadIdx.x; i < 4 * FIN; i += FHID)
            sx[i >> 6][i & 63] = x[(size_t)base * FIN + i];
        __syncthreads();
#pragma unroll
        for (int j = 0; j < 4; j++) {
            float acc = 0.f;
#pragma unroll
            for (int k = 0; k < FIN; k++) acc = fmaf(sx[j][k], w[k], acc);
            g_h1[(size_t)(base + j) * FHID + f] = acc;
        }
        __syncthreads();
    }
}

// h2 = bn(t) @ W2.  thread f keeps W2[:,f] (128 vals) in regs; BN applied on row load.
__global__ void __launch_bounds__(FHID, 3) k_gemm2(const float* __restrict__ W2) {
    __shared__ float su[2][FHID];
    const int f = threadIdx.x;
    float w[FHID];
#pragma unroll
    for (int k = 0; k < FHID; k++) w[k] = W2[k * FHID + f];
    const float scale = g_stats[f];
    const float shift = g_stats[FHID + f];

    for (int base = blockIdx.x * 2; base < NNODES; base += gridDim.x * 2) {
        su[0][f] = fmaf(g_t[(size_t)base * FHID + f], scale, shift);
        su[1][f] = fmaf(g_t[(size_t)(base + 1) * FHID + f], scale, shift);
        __syncthreads();
#pragma unroll
        for (int j = 0; j < 2; j++) {
            float acc = 0.f;
#pragma unroll
            for (int k = 0; k < FHID; k++) acc = fmaf(su[j][k], w[k], acc);
            g_h2[(size_t)(base + j) * FHID + f] = acc;
        }
        __syncthreads();
    }
}

// ---------------- gathers (warp per destination node) ----------------

// t[c] = relu( sum_{e->c} h1[r]*norm + h1[c]*dinv[c]^2 + b1 ); BN partial sums.
__global__ void k_gather1(const float* __restrict__ b1) {
    const int lane = threadIdx.x & 31;                 // feature quad
    const int warp = (blockIdx.x * blockDim.x + threadIdx.x) >> 5;
    const int nwarps = (gridDim.x * blockDim.x) >> 5;
    const float4 bf = reinterpret_cast<const float4*>(b1)[lane];
    const float4* h4 = reinterpret_cast<const float4*>(g_h1);
    float4* t4 = reinterpret_cast<float4*>(g_t);
    float4 s  = make_float4(0.f, 0.f, 0.f, 0.f);
    float4 ss = make_float4(0.f, 0.f, 0.f, 0.f);

    for (int c = warp; c < NNODES; c += nwarps) {
        const int beg = g_off[c], end = g_off[c + 1];
        const float dc = g_dinv[c];
        const float d2 = dc * dc;
        float4 h = h4[(size_t)c * 32 + lane];
        float4 acc = make_float4(h.x * d2, h.y * d2, h.z * d2, h.w * d2);
        for (int i = beg; i < end; i++) {
            const int2 en = g_csr[i];
            const float nm = __int_as_float(en.y);
            const float4 v = h4[(size_t)en.x * 32 + lane];
            acc.x = fmaf(v.x, nm, acc.x);
            acc.y = fmaf(v.y, nm, acc.y);
            acc.z = fmaf(v.z, nm, acc.z);
            acc.w = fmaf(v.w, nm, acc.w);
        }
        acc.x = fmaxf(acc.x + bf.x, 0.f);
        acc.y = fmaxf(acc.y + bf.y, 0.f);
        acc.z = fmaxf(acc.z + bf.z, 0.f);
        acc.w = fmaxf(acc.w + bf.w, 0.f);
        t4[(size_t)c * 32 + lane] = acc;
        s.x += acc.x; s.y += acc.y; s.z += acc.z; s.w += acc.w;
        ss.x += acc.x * acc.x; ss.y += acc.y * acc.y;
        ss.z += acc.z * acc.z; ss.w += acc.w * acc.w;
    }
    float* st = &g_stats[4 * lane];
    atomicAdd(st + 0, s.x); atomicAdd(st + 1, s.y);
    atomicAdd(st + 2, s.z); atomicAdd(st + 3, s.w);
    st = &g_stats[FHID + 4 * lane];
    atomicAdd(st + 0, ss.x); atomicAdd(st + 1, ss.y);
    atomicAdd(st + 2, ss.z); atomicAdd(st + 3, ss.w);
}

// out[c] = relu( sum_{e->c} h2[r]*norm + h2[c]*dinv[c]^2 + b2 )
__global__ void k_gather2(float* __restrict__ out, const float* __restrict__ b2) {
    const int lane = threadIdx.x & 31;
    const int warp = (blockIdx.x * blockDim.x + threadIdx.x) >> 5;
    const int nwarps = (gridDim.x * blockDim.x) >> 5;
    const float4 bf = reinterpret_cast<const float4*>(b2)[lane];
    const float4* h4 = reinterpret_cast<const float4*>(g_h2);
    float4* o4 = reinterpret_cast<float4*>(out);

    for (int c = warp; c < NNODES; c += nwarps) {
        const int beg = g_off[c], end = g_off[c + 1];
        const float dc = g_dinv[c];
        const float d2 = dc * dc;
        float4 h = h4[(size_t)c * 32 + lane];
        float4 acc = make_float4(h.x * d2, h.y * d2, h.z * d2, h.w * d2);
        for (int i = beg; i < end; i++) {
            const int2 en = g_csr[i];
            const float nm = __int_as_float(en.y);
            const float4 v = h4[(size_t)en.x * 32 + lane];
            acc.x = fmaf(v.x, nm, acc.x);
            acc.y = fmaf(v.y, nm, acc.y);
            acc.z = fmaf(v.z, nm, acc.z);
            acc.w = fmaf(v.w, nm, acc.w);
        }
        acc.x = fmaxf(acc.x + bf.x, 0.f);
        acc.y = fmaxf(acc.y + bf.y, 0.f);
        acc.z = fmaxf(acc.z + bf.z, 0.f);
        acc.w = fmaxf(acc.w + bf.w, 0.f);
        o4[(size_t)c * 32 + lane] = acc;
    }
}

// fold BN into per-feature scale/shift
__global__ void k_bnfold(const float* __restrict__ gamma, const float* __restrict__ beta) {
    const int f = threadIdx.x;
    const float inv_n = 1.0f / (float)NNODES;
    const float mean = g_stats[f] * inv_n;
    const float var  = g_stats[FHID + f] * inv_n - mean * mean;
    const float rstd = rsqrtf(var + BN_EPS);
    const float scale = gamma[f] * rstd;
    g_stats[f]        = scale;
    g_stats[FHID + f] = beta[f] - mean * scale;
}

// ---------------- launch ----------------
extern "C" void kernel_launch(void* const* d_in, const int* in_sizes, int n_in,
                              void* d_out, int out_size) {
    const float* x     = (const float*)d_in[0];
    const void*  ei    = d_in[1];                 // [2, E], int32 OR int64 (detected)
    const float* W1    = (const float*)d_in[2];
    const float* b1    = (const float*)d_in[3];
    const float* gamma = (const float*)d_in[4];
    const float* beta  = (const float*)d_in[5];
    const float* W2    = (const float*)d_in[6];
    const float* b2    = (const float*)d_in[7];
    float* out = (float*)d_out;

    k_zero<<<512, 256>>>();
    k_detect<<<1, 256>>>((const int*)ei);
    k_deg<<<2048, 256>>>(ei);
    k_scanA<<<NB_SCAN, 256>>>();
    k_scanC<<<NB_SCAN, 256>>>();
    k_fillcsr<<<2048, 256>>>(ei);

    k_gemm1<<<888, FHID>>>(x, W1);
    k_gather1<<<1184, 256>>>(b1);
    k_bnfold<<<1, FHID>>>(gamma, beta);

    k_gemm2<<<444, FHID>>>(W2);
    k_gather2<<<1184, 256>>>(out, b2);
}

// round 10
// speedup vs baseline: 1.0601x; 1.0326x over previous
#include <cuda_runtime.h>
#include <cuda_bf16.h>
#include <stdint.h>

// GCN_57501022159512: 2-layer GCN, N=100000 nodes, E=1600000 edges, 64 -> 128 -> 128.
// h1 = relu(gcnconv(x, W1, b1)); t = batchnorm(h1); out = relu(gcnconv(t, W2, b2))
//
// R10: (1) gather edge loops manually unrolled x4 for memory-level parallelism
// (loop-carried dependence was limiting MLP; L2-BW floor is ~72us/gather).
// (2) gemm1 and fillcsr are independent -> fused into one launch with
// block-role split (serial stream, free concurrency). (3) detect folded into zero.

#define NNODES 100000
#define NEDGES 1600000
#define FIN    64
#define FHID   128
#define BN_EPS 1e-5f

#define NB_SCAN 100
#define NODES_PER_BLK 1000   // NNODES / NB_SCAN, exact

#define GEMM1_BLOCKS 444
#define FILL_BLOCKS  2048

// ---------------- scratch (device globals; no allocs allowed) ----------------
__device__ float g_h1[NNODES * FHID];    // x @ W1
__device__ float g_t [NNODES * FHID];    // relu/bn input (gather1 output)
__device__ float g_h2[NNODES * FHID];    // bn(t) @ W2
__device__ float g_dinv[NNODES];
__device__ int   g_deg [NNODES];
__device__ float g_stats[2 * FHID];      // sum,sumsq -> then scale,shift
__device__ int   g_off [NNODES + 1];     // CSR offsets (by destination col)
__device__ int   g_cursor[NNODES];       // placement cursors
__device__ int2  g_csr[NEDGES];          // (src row, norm bits) sorted by dest
__device__ int   g_bsum[NB_SCAN];        // per-block degree sums
__device__ int   g_is64;

// ---------------- setup ----------------

// zero deg/stats; block 0 additionally detects edge dtype (int32 vs int64).
__global__ void k_zero_detect(const int* __restrict__ w) {
    const int idx = blockIdx.x * blockDim.x + threadIdx.x;
    const int stride = gridDim.x * blockDim.x;
    for (int j = idx; j < NNODES; j += stride) g_deg[j] = 0;
    if (idx < 2 * FHID) g_stats[idx] = 0.f;

    if (blockIdx.x == 0) {
        __shared__ int bad;
        if (threadIdx.x == 0) bad = 0;
        __syncthreads();
        for (int j = threadIdx.x; j < 1024; j += blockDim.x) {
            const int lo = w[2 * j], hi = w[2 * j + 1];
            if (hi != 0 || lo < 0 || lo >= NNODES) bad = 1;
        }
        __syncthreads();
        if (threadIdx.x == 0) g_is64 = (bad == 0) ? 1 : 0;
    }
}

__device__ __forceinline__ int load_idx(const void* ei, int pos, bool is64) {
    int v = is64 ? (int)((const long long*)ei)[pos] : ((const int*)ei)[pos];
    return min(max(v, 0), NNODES - 1);
}

// Degree count directly from edge buffer (col half).
__global__ void k_deg(const void* __restrict__ ei) {
    const int idx = blockIdx.x * blockDim.x + threadIdx.x;
    const int stride = gridDim.x * blockDim.x;
    const bool is64 = (g_is64 != 0);
    for (int e = idx; e < NEDGES; e += stride)
        atomicAdd(&g_deg[load_idx(ei, NEDGES + e, is64)], 1);
}

// Stage A: per-block degree sums.
__global__ void k_scanA() {
    __shared__ int red[256];
    const int b = blockIdx.x;
    const int t = threadIdx.x;
    const int beg = b * NODES_PER_BLK;
    int s = 0;
    for (int i = t; i < NODES_PER_BLK; i += 256) s += g_deg[beg + i];
    red[t] = s;
    __syncthreads();
    for (int d = 128; d > 0; d >>= 1) {
        if (t < d) red[t] += red[t + d];
        __syncthreads();
    }
    if (t == 0) g_bsum[b] = red[0];
}

// Stage C: offsets + cursors + dinv (fused).
__global__ void k_scanC() {
    __shared__ int red[256];
    __shared__ int partial[256];
    __shared__ int s_base;
    const int b = blockIdx.x;
    const int t = threadIdx.x;
    const int beg = b * NODES_PER_BLK;

    int s = (t < b) ? g_bsum[t] : 0;
    red[t] = s;
    __syncthreads();
    for (int d = 128; d > 0; d >>= 1) {
        if (t < d) red[t] += red[t + d];
        __syncthreads();
    }
    if (t == 0) s_base = red[0];
    __syncthreads();

    const int cbeg = t * 4;
    int csum = 0;
    int dloc[4];
#pragma unroll
    for (int j = 0; j < 4; j++) {
        const int i = cbeg + j;
        dloc[j] = (i < NODES_PER_BLK) ? g_deg[beg + i] : 0;
        csum += dloc[j];
    }
    partial[t] = csum;
    __syncthreads();
    for (int d = 1; d < 256; d <<= 1) {
        int v = (t >= d) ? partial[t - d] : 0;
        __syncthreads();
        partial[t] += v;
        __syncthreads();
    }
    int run = s_base + ((t == 0) ? 0 : partial[t - 1]);
#pragma unroll
    for (int j = 0; j < 4; j++) {
        const int i = cbeg + j;
        if (i < NODES_PER_BLK) {
            g_off[beg + i] = run;
            g_cursor[beg + i] = run;
            g_dinv[beg + i] = rsqrtf((float)(dloc[j] + 1));
            run += dloc[j];
        }
    }
    if (b == NB_SCAN - 1 && t == 255) g_off[NNODES] = run;
}

// ---------------- fused gemm1 + fillcsr (independent work, one launch) -------
// Blocks [0, GEMM1_BLOCKS): h1 = x @ W1 (256 thr: half h handles 4 rows, f = t&127).
// Blocks [GEMM1_BLOCKS, +FILL_BLOCKS): counting sort into g_csr.
__global__ void __launch_bounds__(256) k_gemm1_fillcsr(const float* __restrict__ x,
                                                       const float* __restrict__ W1,
                                                       const void* __restrict__ ei) {
    if (blockIdx.x < GEMM1_BLOCKS) {
        __shared__ float sx[8][FIN];
        const int t = threadIdx.x;
        const int f = t & 127;
        const int half = t >> 7;            // 0 or 1
        float w[FIN];
#pragma unroll
        for (int k = 0; k < FIN; k++) w[k] = W1[k * FHID + f];

        for (int base = blockIdx.x * 8; base < NNODES; base += GEMM1_BLOCKS * 8) {
            for (int i = t; i < 8 * FIN; i += 256)
                sx[i >> 6][i & 63] = x[(size_t)base * FIN + i];
            __syncthreads();
            const int rbase = half * 4;
#pragma unroll
            for (int j = 0; j < 4; j++) {
                float acc = 0.f;
#pragma unroll
                for (int k = 0; k < FIN; k++) acc = fmaf(sx[rbase + j][k], w[k], acc);
                const int node = base + rbase + j;
                if (node < NNODES)
                    g_h1[(size_t)node * FHID + f] = acc;
            }
            __syncthreads();
        }
    } else {
        const int vb = blockIdx.x - GEMM1_BLOCKS;
        const int idx = vb * 256 + threadIdx.x;
        const int stride = FILL_BLOCKS * 256;
        const bool is64 = (g_is64 != 0);
        for (int e = idx; e < NEDGES; e += stride) {
            const int r = load_idx(ei, e, is64);
            const int c = load_idx(ei, NEDGES + e, is64);
            const int pos = atomicAdd(&g_cursor[c], 1);
            const float nm = g_dinv[r] * g_dinv[c];
            g_csr[pos] = make_int2(r, __float_as_int(nm));
        }
    }
}

// ---------------- GEMM2 (scalar FFMA, at roofline) ----------------
__global__ void __launch_bounds__(FHID, 3) k_gemm2(const float* __restrict__ W2) {
    __shared__ float su[2][FHID];
    const int f = threadIdx.x;
    float w[FHID];
#pragma unroll
    for (int k = 0; k < FHID; k++) w[k] = W2[k * FHID + f];
    const float scale = g_stats[f];
    const float shift = g_stats[FHID + f];

    for (int base = blockIdx.x * 2; base < NNODES; base += gridDim.x * 2) {
        su[0][f] = fmaf(g_t[(size_t)base * FHID + f], scale, shift);
        su[1][f] = fmaf(g_t[(size_t)(base + 1) * FHID + f], scale, shift);
        __syncthreads();
#pragma unroll
        for (int j = 0; j < 2; j++) {
            float acc = 0.f;
#pragma unroll
            for (int k = 0; k < FHID; k++) acc = fmaf(su[j][k], w[k], acc);
            g_h2[(size_t)(base + j) * FHID + f] = acc;
        }
        __syncthreads();
    }
}

// ---------------- gathers (warp per destination node, edge loop unrolled x4) --

__device__ __forceinline__ float4 gather_node(const float4* __restrict__ h4,
                                              int c, int lane) {
    const int beg = g_off[c], end = g_off[c + 1];
    const float dc = g_dinv[c];
    const float d2 = dc * dc;
    const float4 h = h4[(size_t)c * 32 + lane];
    float4 acc = make_float4(h.x * d2, h.y * d2, h.z * d2, h.w * d2);
    int i = beg;
    for (; i + 4 <= end; i += 4) {
        const int2 ea = g_csr[i];
        const int2 eb = g_csr[i + 1];
        const int2 ec = g_csr[i + 2];
        const int2 ed = g_csr[i + 3];
        const float4 va = h4[(size_t)ea.x * 32 + lane];
        const float4 vb = h4[(size_t)eb.x * 32 + lane];
        const float4 vc = h4[(size_t)ec.x * 32 + lane];
        const float4 vd = h4[(size_t)ed.x * 32 + lane];
        const float na = __int_as_float(ea.y);
        const float nb = __int_as_float(eb.y);
        const float nc = __int_as_float(ec.y);
        const float nd = __int_as_float(ed.y);
        acc.x = fmaf(va.x, na, acc.x); acc.y = fmaf(va.y, na, acc.y);
        acc.z = fmaf(va.z, na, acc.z); acc.w = fmaf(va.w, na, acc.w);
        acc.x = fmaf(vb.x, nb, acc.x); acc.y = fmaf(vb.y, nb, acc.y);
        acc.z = fmaf(vb.z, nb, acc.z); acc.w = fmaf(vb.w, nb, acc.w);
        acc.x = fmaf(vc.x, nc, acc.x); acc.y = fmaf(vc.y, nc, acc.y);
        acc.z = fmaf(vc.z, nc, acc.z); acc.w = fmaf(vc.w, nc, acc.w);
        acc.x = fmaf(vd.x, nd, acc.x); acc.y = fmaf(vd.y, nd, acc.y);
        acc.z = fmaf(vd.z, nd, acc.z); acc.w = fmaf(vd.w, nd, acc.w);
    }
    for (; i < end; i++) {
        const int2 en = g_csr[i];
        const float nm = __int_as_float(en.y);
        const float4 v = h4[(size_t)en.x * 32 + lane];
        acc.x = fmaf(v.x, nm, acc.x); acc.y = fmaf(v.y, nm, acc.y);
        acc.z = fmaf(v.z, nm, acc.z); acc.w = fmaf(v.w, nm, acc.w);
    }
    return acc;
}

// t[c] = relu(gather + b1); BN partial sums.
__global__ void k_gather1(const float* __restrict__ b1) {
    const int lane = threadIdx.x & 31;
    const int warp = (blockIdx.x * blockDim.x + threadIdx.x) >> 5;
    const int nwarps = (gridDim.x * blockDim.x) >> 5;
    const float4 bf = reinterpret_cast<const float4*>(b1)[lane];
    const float4* h4 = reinterpret_cast<const float4*>(g_h1);
    float4* t4 = reinterpret_cast<float4*>(g_t);
    float4 s  = make_float4(0.f, 0.f, 0.f, 0.f);
    float4 ss = make_float4(0.f, 0.f, 0.f, 0.f);

    for (int c = warp; c < NNODES; c += nwarps) {
        float4 acc = gather_node(h4, c, lane);
        acc.x = fmaxf(acc.x + bf.x, 0.f);
        acc.y = fmaxf(acc.y + bf.y, 0.f);
        acc.z = fmaxf(acc.z + bf.z, 0.f);
        acc.w = fmaxf(acc.w + bf.w, 0.f);
        t4[(size_t)c * 32 + lane] = acc;
        s.x += acc.x; s.y += acc.y; s.z += acc.z; s.w += acc.w;
        ss.x += acc.x * acc.x; ss.y += acc.y * acc.y;
        ss.z += acc.z * acc.z; ss.w += acc.w * acc.w;
    }
    float* st = &g_stats[4 * lane];
    atomicAdd(st + 0, s.x); atomicAdd(st + 1, s.y);
    atomicAdd(st + 2, s.z); atomicAdd(st + 3, s.w);
    st = &g_stats[FHID + 4 * lane];
    atomicAdd(st + 0, ss.x); atomicAdd(st + 1, ss.y);
    atomicAdd(st + 2, ss.z); atomicAdd(st + 3, ss.w);
}

// out[c] = relu(gather + b2)
__global__ void k_gather2(float* __restrict__ out, const float* __restrict__ b2) {
    const int lane = threadIdx.x & 31;
    const int warp = (blockIdx.x * blockDim.x + threadIdx.x) >> 5;
    const int nwarps = (gridDim.x * blockDim.x) >> 5;
    const float4 bf = reinterpret_cast<const float4*>(b2)[lane];
    const float4* h4 = reinterpret_cast<const float4*>(g_h2);
    float4* o4 = reinterpret_cast<float4*>(out);

    for (int c = warp; c < NNODES; c += nwarps) {
        float4 acc = gather_node(h4, c, lane);
        acc.x = fmaxf(acc.x + bf.x, 0.f);
        acc.y = fmaxf(acc.y + bf.y, 0.f);
        acc.z = fmaxf(acc.z + bf.z, 0.f);
        acc.w = fmaxf(acc.w + bf.w, 0.f);
        o4[(size_t)c * 32 + lane] = acc;
    }
}

// fold BN into per-feature scale/shift
__global__ void k_bnfold(const float* __restrict__ gamma, const float* __restrict__ beta) {
    const int f = threadIdx.x;
    const float inv_n = 1.0f / (float)NNODES;
    const float mean = g_stats[f] * inv_n;
    const float var  = g_stats[FHID + f] * inv_n - mean * mean;
    const float rstd = rsqrtf(var + BN_EPS);
    const float scale = gamma[f] * rstd;
    g_stats[f]        = scale;
    g_stats[FHID + f] = beta[f] - mean * scale;
}

// ---------------- launch ----------------
extern "C" void kernel_launch(void* const* d_in, const int* in_sizes, int n_in,
                              void* d_out, int out_size) {
    const float* x     = (const float*)d_in[0];
    const void*  ei    = d_in[1];                 // [2, E], int32 OR int64 (detected)
    const float* W1    = (const float*)d_in[2];
    const float* b1    = (const float*)d_in[3];
    const float* gamma = (const float*)d_in[4];
    const float* beta  = (const float*)d_in[5];
    const float* W2    = (const float*)d_in[6];
    const float* b2    = (const float*)d_in[7];
    float* out = (float*)d_out;

    k_zero_detect<<<512, 256>>>((const int*)ei);
    k_deg<<<2048, 256>>>(ei);
    k_scanA<<<NB_SCAN, 256>>>();
    k_scanC<<<NB_SCAN, 256>>>();
    k_gemm1_fillcsr<<<GEMM1_BLOCKS + FILL_BLOCKS, 256>>>(x, W1, ei);
    k_gather1<<<1184, 256>>>(b1);
    k_bnfold<<<1, FHID>>>(gamma, beta);
    k_gemm2<<<444, FHID>>>(W2);
    k_gather2<<<1184, 256>>>(out, b2);
}

// round 11
// speedup vs baseline: 1.1372x; 1.0727x over previous
#include <cuda_runtime.h>
#include <cuda_fp16.h>
#include <stdint.h>

// GCN_57501022159512: 2-layer GCN, N=100000 nodes, E=1600000 edges, 64 -> 128 -> 128.
// h1 = relu(gcnconv(x, W1, b1)); t = batchnorm(h1); out = relu(gcnconv(t, W2, b2))
//
// R11: gather inputs (h1, h2) staged in fp16 -> gather L2 read traffic halved
// (820MB -> 410MB per layer). Accumulation stays fp32. bnfold folded into
// gemm2 prologue. Everything else as R10 (fused gemm1+fillcsr, x4 unroll).

#define NNODES 100000
#define NEDGES 1600000
#define FIN    64
#define FHID   128
#define BN_EPS 1e-5f

#define NB_SCAN 100
#define NODES_PER_BLK 1000   // NNODES / NB_SCAN, exact

#define GEMM1_BLOCKS 444
#define FILL_BLOCKS  2048

// ---------------- scratch (device globals; no allocs allowed) ----------------
__device__ __half2 g_h1[NNODES * (FHID / 2)];  // x @ W1 (fp16 staged)
__device__ float   g_t [NNODES * FHID];        // gather1 output (fp32)
__device__ __half2 g_h2[NNODES * (FHID / 2)];  // bn(t) @ W2 (fp16 staged)
__device__ float   g_dinv[NNODES];
__device__ int     g_deg [NNODES];
__device__ float   g_stats[2 * FHID];          // sum,sumsq
__device__ int     g_off [NNODES + 1];         // CSR offsets (by destination col)
__device__ int     g_cursor[NNODES];           // placement cursors
__device__ int2    g_csr[NEDGES];              // (src row, norm bits) sorted by dest
__device__ int     g_bsum[NB_SCAN];            // per-block degree sums
__device__ int     g_is64;

// ---------------- helpers ----------------

__device__ __forceinline__ float4 h8_to_f4(uint2 u) {
    const __half2 a = *reinterpret_cast<__half2*>(&u.x);
    const __half2 b = *reinterpret_cast<__half2*>(&u.y);
    const float2 fa = __half22float2(a);
    const float2 fb = __half22float2(b);
    return make_float4(fa.x, fa.y, fb.x, fb.y);
}

__device__ __forceinline__ int load_idx(const void* ei, int pos, bool is64) {
    int v = is64 ? (int)((const long long*)ei)[pos] : ((const int*)ei)[pos];
    return min(max(v, 0), NNODES - 1);
}

// ---------------- setup ----------------

// zero deg/stats; block 0 additionally detects edge dtype (int32 vs int64).
__global__ void k_zero_detect(const int* __restrict__ w) {
    const int idx = blockIdx.x * blockDim.x + threadIdx.x;
    const int stride = gridDim.x * blockDim.x;
    for (int j = idx; j < NNODES; j += stride) g_deg[j] = 0;
    if (idx < 2 * FHID) g_stats[idx] = 0.f;

    if (blockIdx.x == 0) {
        __shared__ int bad;
        if (threadIdx.x == 0) bad = 0;
        __syncthreads();
        for (int j = threadIdx.x; j < 1024; j += blockDim.x) {
            const int lo = w[2 * j], hi = w[2 * j + 1];
            if (hi != 0 || lo < 0 || lo >= NNODES) bad = 1;
        }
        __syncthreads();
        if (threadIdx.x == 0) g_is64 = (bad == 0) ? 1 : 0;
    }
}

// Degree count directly from edge buffer (col half).
__global__ void k_deg(const void* __restrict__ ei) {
    const int idx = blockIdx.x * blockDim.x + threadIdx.x;
    const int stride = gridDim.x * blockDim.x;
    const bool is64 = (g_is64 != 0);
    for (int e = idx; e < NEDGES; e += stride)
        atomicAdd(&g_deg[load_idx(ei, NEDGES + e, is64)], 1);
}

// Stage A: per-block degree sums.
__global__ void k_scanA() {
    __shared__ int red[256];
    const int b = blockIdx.x;
    const int t = threadIdx.x;
    const int beg = b * NODES_PER_BLK;
    int s = 0;
    for (int i = t; i < NODES_PER_BLK; i += 256) s += g_deg[beg + i];
    red[t] = s;
    __syncthreads();
    for (int d = 128; d > 0; d >>= 1) {
        if (t < d) red[t] += red[t + d];
        __syncthreads();
    }
    if (t == 0) g_bsum[b] = red[0];
}

// Stage C: offsets + cursors + dinv (fused).
__global__ void k_scanC() {
    __shared__ int red[256];
    __shared__ int partial[256];
    __shared__ int s_base;
    const int b = blockIdx.x;
    const int t = threadIdx.x;
    const int beg = b * NODES_PER_BLK;

    int s = (t < b) ? g_bsum[t] : 0;
    red[t] = s;
    __syncthreads();
    for (int d = 128; d > 0; d >>= 1) {
        if (t < d) red[t] += red[t + d];
        __syncthreads();
    }
    if (t == 0) s_base = red[0];
    __syncthreads();

    const int cbeg = t * 4;
    int csum = 0;
    int dloc[4];
#pragma unroll
    for (int j = 0; j < 4; j++) {
        const int i = cbeg + j;
        dloc[j] = (i < NODES_PER_BLK) ? g_deg[beg + i] : 0;
        csum += dloc[j];
    }
    partial[t] = csum;
    __syncthreads();
    for (int d = 1; d < 256; d <<= 1) {
        int v = (t >= d) ? partial[t - d] : 0;
        __syncthreads();
        partial[t] += v;
        __syncthreads();
    }
    int run = s_base + ((t == 0) ? 0 : partial[t - 1]);
#pragma unroll
    for (int j = 0; j < 4; j++) {
        const int i = cbeg + j;
        if (i < NODES_PER_BLK) {
            g_off[beg + i] = run;
            g_cursor[beg + i] = run;
            g_dinv[beg + i] = rsqrtf((float)(dloc[j] + 1));
            run += dloc[j];
        }
    }
    if (b == NB_SCAN - 1 && t == 255) g_off[NNODES] = run;
}

// ---------------- fused gemm1 + fillcsr ----------------
__global__ void __launch_bounds__(256) k_gemm1_fillcsr(const float* __restrict__ x,
                                                       const float* __restrict__ W1,
                                                       const void* __restrict__ ei) {
    if (blockIdx.x < GEMM1_BLOCKS) {
        __shared__ float sx[8][FIN];
        const int t = threadIdx.x;
        const int f = t & 127;
        const int half = t >> 7;            // 0 or 1
        float w[FIN];
#pragma unroll
        for (int k = 0; k < FIN; k++) w[k] = W1[k * FHID + f];
        __half* h1h = reinterpret_cast<__half*>(g_h1);

        for (int base = blockIdx.x * 8; base < NNODES; base += GEMM1_BLOCKS * 8) {
            for (int i = t; i < 8 * FIN; i += 256)
                sx[i >> 6][i & 63] = x[(size_t)base * FIN + i];
            __syncthreads();
            const int rbase = half * 4;
#pragma unroll
            for (int j = 0; j < 4; j++) {
                float acc = 0.f;
#pragma unroll
                for (int k = 0; k < FIN; k++) acc = fmaf(sx[rbase + j][k], w[k], acc);
                const int node = base + rbase + j;
                if (node < NNODES)
                    h1h[(size_t)node * FHID + f] = __float2half_rn(acc);
            }
            __syncthreads();
        }
    } else {
        const int vb = blockIdx.x - GEMM1_BLOCKS;
        const int idx = vb * 256 + threadIdx.x;
        const int stride = FILL_BLOCKS * 256;
        const bool is64 = (g_is64 != 0);
        for (int e = idx; e < NEDGES; e += stride) {
            const int r = load_idx(ei, e, is64);
            const int c = load_idx(ei, NEDGES + e, is64);
            const int pos = atomicAdd(&g_cursor[c], 1);
            const float nm = g_dinv[r] * g_dinv[c];
            g_csr[pos] = make_int2(r, __float_as_int(nm));
        }
    }
}

// ---------------- GEMM2 (scalar FFMA; BN fold inline) ----------------
__global__ void __launch_bounds__(FHID, 3) k_gemm2(const float* __restrict__ W2,
                                                   const float* __restrict__ gamma,
                                                   const float* __restrict__ beta) {
    __shared__ float su[2][FHID];
    const int f = threadIdx.x;
    float w[FHID];
#pragma unroll
    for (int k = 0; k < FHID; k++) w[k] = W2[k * FHID + f];

    // fold BN (redundant per block; trivially cheap)
    const float inv_n = 1.0f / (float)NNODES;
    const float mean = g_stats[f] * inv_n;
    const float var  = g_stats[FHID + f] * inv_n - mean * mean;
    const float rstd = rsqrtf(var + BN_EPS);
    const float scale = gamma[f] * rstd;
    const float shift = beta[f] - mean * scale;

    __half* h2h = reinterpret_cast<__half*>(g_h2);

    for (int base = blockIdx.x * 2; base < NNODES; base += gridDim.x * 2) {
        su[0][f] = fmaf(g_t[(size_t)base * FHID + f], scale, shift);
        su[1][f] = fmaf(g_t[(size_t)(base + 1) * FHID + f], scale, shift);
        __syncthreads();
#pragma unroll
        for (int j = 0; j < 2; j++) {
            float acc = 0.f;
#pragma unroll
            for (int k = 0; k < FHID; k++) acc = fmaf(su[j][k], w[k], acc);
            h2h[(size_t)(base + j) * FHID + f] = __float2half_rn(acc);
        }
        __syncthreads();
    }
}

// ---------------- gathers (warp per destination, fp16 rows, unroll x4) -------

__device__ __forceinline__ float4 gather_node(const uint2* __restrict__ hp,
                                              int c, int lane) {
    const int beg = g_off[c], end = g_off[c + 1];
    const float dc = g_dinv[c];
    const float d2 = dc * dc;
    const float4 h = h8_to_f4(hp[(size_t)c * 32 + lane]);
    float4 acc = make_float4(h.x * d2, h.y * d2, h.z * d2, h.w * d2);
    int i = beg;
    for (; i + 4 <= end; i += 4) {
        const int2 ea = g_csr[i];
        const int2 eb = g_csr[i + 1];
        const int2 ec = g_csr[i + 2];
        const int2 ed = g_csr[i + 3];
        const float4 va = h8_to_f4(hp[(size_t)ea.x * 32 + lane]);
        const float4 vb = h8_to_f4(hp[(size_t)eb.x * 32 + lane]);
        const float4 vc = h8_to_f4(hp[(size_t)ec.x * 32 + lane]);
        const float4 vd = h8_to_f4(hp[(size_t)ed.x * 32 + lane]);
        const float na = __int_as_float(ea.y);
        const float nb = __int_as_float(eb.y);
        const float nc = __int_as_float(ec.y);
        const float nd = __int_as_float(ed.y);
        acc.x = fmaf(va.x, na, acc.x); acc.y = fmaf(va.y, na, acc.y);
        acc.z = fmaf(va.z, na, acc.z); acc.w = fmaf(va.w, na, acc.w);
        acc.x = fmaf(vb.x, nb, acc.x); acc.y = fmaf(vb.y, nb, acc.y);
        acc.z = fmaf(vb.z, nb, acc.z); acc.w = fmaf(vb.w, nb, acc.w);
        acc.x = fmaf(vc.x, nc, acc.x); acc.y = fmaf(vc.y, nc, acc.y);
        acc.z = fmaf(vc.z, nc, acc.z); acc.w = fmaf(vc.w, nc, acc.w);
        acc.x = fmaf(vd.x, nd, acc.x); acc.y = fmaf(vd.y, nd, acc.y);
        acc.z = fmaf(vd.z, nd, acc.z); acc.w = fmaf(vd.w, nd, acc.w);
    }
    for (; i < end; i++) {
        const int2 en = g_csr[i];
        const float nm = __int_as_float(en.y);
        const float4 v = h8_to_f4(hp[(size_t)en.x * 32 + lane]);
        acc.x = fmaf(v.x, nm, acc.x); acc.y = fmaf(v.y, nm, acc.y);
        acc.z = fmaf(v.z, nm, acc.z); acc.w = fmaf(v.w, nm, acc.w);
    }
    return acc;
}

// t[c] = relu(gather(h1) + b1); BN partial sums.
__global__ void k_gather1(const float* __restrict__ b1) {
    const int lane = threadIdx.x & 31;
    const int warp = (blockIdx.x * blockDim.x + threadIdx.x) >> 5;
    const int nwarps = (gridDim.x * blockDim.x) >> 5;
    const float4 bf = reinterpret_cast<const float4*>(b1)[lane];
    const uint2* hp = reinterpret_cast<const uint2*>(g_h1);
    float4* t4 = reinterpret_cast<float4*>(g_t);
    float4 s  = make_float4(0.f, 0.f, 0.f, 0.f);
    float4 ss = make_float4(0.f, 0.f, 0.f, 0.f);

    for (int c = warp; c < NNODES; c += nwarps) {
        float4 acc = gather_node(hp, c, lane);
        acc.x = fmaxf(acc.x + bf.x, 0.f);
        acc.y = fmaxf(acc.y + bf.y, 0.f);
        acc.z = fmaxf(acc.z + bf.z, 0.f);
        acc.w = fmaxf(acc.w + bf.w, 0.f);
        t4[(size_t)c * 32 + lane] = acc;
        s.x += acc.x; s.y += acc.y; s.z += acc.z; s.w += acc.w;
        ss.x += acc.x * acc.x; ss.y += acc.y * acc.y;
        ss.z += acc.z * acc.z; ss.w += acc.w * acc.w;
    }
    float* st = &g_stats[4 * lane];
    atomicAdd(st + 0, s.x); atomicAdd(st + 1, s.y);
    atomicAdd(st + 2, s.z); atomicAdd(st + 3, s.w);
    st = &g_stats[FHID + 4 * lane];
    atomicAdd(st + 0, ss.x); atomicAdd(st + 1, ss.y);
    atomicAdd(st + 2, ss.z); atomicAdd(st + 3, ss.w);
}

// out[c] = relu(gather(h2) + b2)
__global__ void k_gather2(float* __restrict__ out, const float* __restrict__ b2) {
    const int lane = threadIdx.x & 31;
    const int warp = (blockIdx.x * blockDim.x + threadIdx.x) >> 5;
    const int nwarps = (gridDim.x * blockDim.x) >> 5;
    const float4 bf = reinterpret_cast<const float4*>(b2)[lane];
    const uint2* hp = reinterpret_cast<const uint2*>(g_h2);
    float4* o4 = reinterpret_cast<float4*>(out);

    for (int c = warp; c < NNODES; c += nwarps) {
        float4 acc = gather_node(hp, c, lane);
        acc.x = fmaxf(acc.x + bf.x, 0.f);
        acc.y = fmaxf(acc.y + bf.y, 0.f);
        acc.z = fmaxf(acc.z + bf.z, 0.f);
        acc.w = fmaxf(acc.w + bf.w, 0.f);
        o4[(size_t)c * 32 + lane] = acc;
    }
}

// ---------------- launch ----------------
extern "C" void kernel_launch(void* const* d_in, const int* in_sizes, int n_in,
                              void* d_out, int out_size) {
    const float* x     = (const float*)d_in[0];
    const void*  ei    = d_in[1];                 // [2, E], int32 OR int64 (detected)
    const float* W1    = (const float*)d_in[2];
    const float* b1    = (const float*)d_in[3];
    const float* gamma = (const float*)d_in[4];
    const float* beta  = (const float*)d_in[5];
    const float* W2    = (const float*)d_in[6];
    const float* b2    = (const float*)d_in[7];
    float* out = (float*)d_out;

    k_zero_detect<<<512, 256>>>((const int*)ei);
    k_deg<<<2048, 256>>>(ei);
    k_scanA<<<NB_SCAN, 256>>>();
    k_scanC<<<NB_SCAN, 256>>>();
    k_gemm1_fillcsr<<<GEMM1_BLOCKS + FILL_BLOCKS, 256>>>(x, W1, ei);
    k_gather1<<<1184, 256>>>(b1);
    k_gemm2<<<444, FHID>>>(W2, gamma, beta);
    k_gather2<<<1184, 256>>>(out, b2);
}

// round 12
// speedup vs baseline: 1.2506x; 1.0998x over previous
#include <cuda_runtime.h>
#include <cuda_fp16.h>
#include <mma.h>
#include <stdint.h>

using namespace nvcuda;

// GCN_57501022159512: 2-layer GCN, N=100000 nodes, E=1600000 edges, 64 -> 128 -> 128.
// h1 = relu(gcnconv(x, W1, b1)); t = batchnorm(h1); out = relu(gcnconv(t, W2, b2))
//
// R12: gemm2 moved to tensor cores (wmma m16n16k16, fp16 in / fp32 acc).
// A = bn(t) converted to fp16 in smem; W2 pre-converted to fp16 global in
// k_zero_detect; output stored fp16 straight into g_h2 (already fp16-staged
// for gather2 since R11). gemm2 was the last FFMA-roofline kernel (~95us).

#define NNODES 100000
#define NEDGES 1600000
#define FIN    64
#define FHID   128
#define BN_EPS 1e-5f

#define MPAD   100032          // NNODES rounded up to 64 (gemm2 M-tile)

#define NB_SCAN 100
#define NODES_PER_BLK 1000     // NNODES / NB_SCAN, exact

#define GEMM1_BLOCKS 444
#define FILL_BLOCKS  2048

// ---------------- scratch (device globals; no allocs allowed) ----------------
__device__ __half2 g_h1[NNODES * (FHID / 2)];  // x @ W1 (fp16 staged)
__device__ float   g_t [MPAD * FHID];          // gather1 output (fp32, padded)
__device__ __half2 g_h2[MPAD * (FHID / 2)];    // bn(t) @ W2 (fp16, padded)
__device__ __half  g_W2h[FHID * FHID];         // W2 in fp16 (row-major K x N)
__device__ float   g_dinv[NNODES];
__device__ int     g_deg [NNODES];
__device__ float   g_stats[2 * FHID];          // sum,sumsq
__device__ int     g_off [NNODES + 1];         // CSR offsets (by destination col)
__device__ int     g_cursor[NNODES];           // placement cursors
__device__ int2    g_csr[NEDGES];              // (src row, norm bits) sorted by dest
__device__ int     g_bsum[NB_SCAN];            // per-block degree sums
__device__ int     g_is64;

// ---------------- helpers ----------------

__device__ __forceinline__ float4 h8_to_f4(uint2 u) {
    const __half2 a = *reinterpret_cast<__half2*>(&u.x);
    const __half2 b = *reinterpret_cast<__half2*>(&u.y);
    const float2 fa = __half22float2(a);
    const float2 fb = __half22float2(b);
    return make_float4(fa.x, fa.y, fb.x, fb.y);
}

__device__ __forceinline__ int load_idx(const void* ei, int pos, bool is64) {
    int v = is64 ? (int)((const long long*)ei)[pos] : ((const int*)ei)[pos];
    return min(max(v, 0), NNODES - 1);
}

// ---------------- setup ----------------

// zero deg/stats; convert W2 -> fp16; block 0 detects edge dtype.
__global__ void k_zero_detect(const int* __restrict__ w, const float* __restrict__ W2) {
    const int idx = blockIdx.x * blockDim.x + threadIdx.x;
    const int stride = gridDim.x * blockDim.x;
    for (int j = idx; j < NNODES; j += stride) g_deg[j] = 0;
    for (int j = idx; j < FHID * FHID; j += stride) g_W2h[j] = __float2half_rn(W2[j]);
    if (idx < 2 * FHID) g_stats[idx] = 0.f;

    if (blockIdx.x == 0) {
        __shared__ int bad;
        if (threadIdx.x == 0) bad = 0;
        __syncthreads();
        for (int j = threadIdx.x; j < 1024; j += blockDim.x) {
            const int lo = w[2 * j], hi = w[2 * j + 1];
            if (hi != 0 || lo < 0 || lo >= NNODES) bad = 1;
        }
        __syncthreads();
        if (threadIdx.x == 0) g_is64 = (bad == 0) ? 1 : 0;
    }
}

// Degree count directly from edge buffer (col half).
__global__ void k_deg(const void* __restrict__ ei) {
    const int idx = blockIdx.x * blockDim.x + threadIdx.x;
    const int stride = gridDim.x * blockDim.x;
    const bool is64 = (g_is64 != 0);
    for (int e = idx; e < NEDGES; e += stride)
        atomicAdd(&g_deg[load_idx(ei, NEDGES + e, is64)], 1);
}

// Stage A: per-block degree sums.
__global__ void k_scanA() {
    __shared__ int red[256];
    const int b = blockIdx.x;
    const int t = threadIdx.x;
    const int beg = b * NODES_PER_BLK;
    int s = 0;
    for (int i = t; i < NODES_PER_BLK; i += 256) s += g_deg[beg + i];
    red[t] = s;
    __syncthreads();
    for (int d = 128; d > 0; d >>= 1) {
        if (t < d) red[t] += red[t + d];
        __syncthreads();
    }
    if (t == 0) g_bsum[b] = red[0];
}

// Stage C: offsets + cursors + dinv (fused).
__global__ void k_scanC() {
    __shared__ int red[256];
    __shared__ int partial[256];
    __shared__ int s_base;
    const int b = blockIdx.x;
    const int t = threadIdx.x;
    const int beg = b * NODES_PER_BLK;

    int s = (t < b) ? g_bsum[t] : 0;
    red[t] = s;
    __syncthreads();
    for (int d = 128; d > 0; d >>= 1) {
        if (t < d) red[t] += red[t + d];
        __syncthreads();
    }
    if (t == 0) s_base = red[0];
    __syncthreads();

    const int cbeg = t * 4;
    int csum = 0;
    int dloc[4];
#pragma unroll
    for (int j = 0; j < 4; j++) {
        const int i = cbeg + j;
        dloc[j] = (i < NODES_PER_BLK) ? g_deg[beg + i] : 0;
        csum += dloc[j];
    }
    partial[t] = csum;
    __syncthreads();
    for (int d = 1; d < 256; d <<= 1) {
        int v = (t >= d) ? partial[t - d] : 0;
        __syncthreads();
        partial[t] += v;
        __syncthreads();
    }
    int run = s_base + ((t == 0) ? 0 : partial[t - 1]);
#pragma unroll
    for (int j = 0; j < 4; j++) {
        const int i = cbeg + j;
        if (i < NODES_PER_BLK) {
            g_off[beg + i] = run;
            g_cursor[beg + i] = run;
            g_dinv[beg + i] = rsqrtf((float)(dloc[j] + 1));
            run += dloc[j];
        }
    }
    if (b == NB_SCAN - 1 && t == 255) g_off[NNODES] = run;
}

// ---------------- fused gemm1 + fillcsr ----------------
__global__ void __launch_bounds__(256) k_gemm1_fillcsr(const float* __restrict__ x,
                                                       const float* __restrict__ W1,
                                                       const void* __restrict__ ei) {
    if (blockIdx.x < GEMM1_BLOCKS) {
        __shared__ float sx[8][FIN];
        const int t = threadIdx.x;
        const int f = t & 127;
        const int half = t >> 7;            // 0 or 1
        float w[FIN];
#pragma unroll
        for (int k = 0; k < FIN; k++) w[k] = W1[k * FHID + f];
        __half* h1h = reinterpret_cast<__half*>(g_h1);

        for (int base = blockIdx.x * 8; base < NNODES; base += GEMM1_BLOCKS * 8) {
            for (int i = t; i < 8 * FIN; i += 256)
                sx[i >> 6][i & 63] = x[(size_t)base * FIN + i];
            __syncthreads();
            const int rbase = half * 4;
#pragma unroll
            for (int j = 0; j < 4; j++) {
                float acc = 0.f;
#pragma unroll
                for (int k = 0; k < FIN; k++) acc = fmaf(sx[rbase + j][k], w[k], acc);
                const int node = base + rbase + j;
                if (node < NNODES)
                    h1h[(size_t)node * FHID + f] = __float2half_rn(acc);
            }
            __syncthreads();
        }
    } else {
        const int vb = blockIdx.x - GEMM1_BLOCKS;
        const int idx = vb * 256 + threadIdx.x;
        const int stride = FILL_BLOCKS * 256;
        const bool is64 = (g_is64 != 0);
        for (int e = idx; e < NEDGES; e += stride) {
            const int r = load_idx(ei, e, is64);
            const int c = load_idx(ei, NEDGES + e, is64);
            const int pos = atomicAdd(&g_cursor[c], 1);
            const float nm = g_dinv[r] * g_dinv[c];
            g_csr[pos] = make_int2(r, __float_as_int(nm));
        }
    }
}

// ---------------- GEMM2 on tensor cores (wmma fp16 / fp32 acc) ----------------
// Block: 256 threads (8 warps), one 64-row M-tile. Warp w owns N-columns
// [16w, 16w+16). A = fp16(bn(t)) staged in smem; B frags from fp16 W2 global.
__global__ void __launch_bounds__(256) k_gemm2_mma(const float* __restrict__ gamma,
                                                   const float* __restrict__ beta) {
    __shared__ __half  sA[64 * FHID];       // 16 KB
    __shared__ float   sScale[FHID], sShift[FHID];
    const int t = threadIdx.x;
    const int warp = t >> 5;
    const int base = blockIdx.x * 64;

    if (t < FHID) {
        const float inv_n = 1.0f / (float)NNODES;
        const float mean = g_stats[t] * inv_n;
        const float var  = g_stats[FHID + t] * inv_n - mean * mean;
        const float rstd = rsqrtf(var + BN_EPS);
        const float sc = gamma[t] * rstd;
        sScale[t] = sc;
        sShift[t] = beta[t] - mean * sc;
    }
    __syncthreads();

    // Stage A: 64 x 128 fp16 with BN applied (g_t padded; padding rows are 0).
    for (int i = t; i < 64 * FHID; i += 256) {
        const int c = i & 127;
        const float v = g_t[(size_t)(base + (i >> 7)) * FHID + c];
        sA[i] = __float2half_rn(fmaf(v, sScale[c], sShift[c]));
    }
    __syncthreads();

    // Preload all 8 B k-frags for this warp's N-slice.
    wmma::fragment<wmma::matrix_b, 16, 16, 16, __half, wmma::row_major> bf[8];
#pragma unroll
    for (int k = 0; k < 8; k++)
        wmma::load_matrix_sync(bf[k], g_W2h + (k * 16) * FHID + warp * 16, FHID);

    __half* h2 = reinterpret_cast<__half*>(g_h2);
#pragma unroll
    for (int m = 0; m < 4; m++) {
        wmma::fragment<wmma::accumulator, 16, 16, 16, float> acc;
        wmma::fill_fragment(acc, 0.0f);
#pragma unroll
        for (int k = 0; k < 8; k++) {
            wmma::fragment<wmma::matrix_a, 16, 16, 16, __half, wmma::row_major> af;
            wmma::load_matrix_sync(af, sA + (m * 16) * FHID + k * 16, FHID);
            wmma::mma_sync(acc, af, bf[k], acc);
        }
        wmma::fragment<wmma::accumulator, 16, 16, 16, __half> hacc;
#pragma unroll
        for (int i = 0; i < acc.num_elements; i++)
            hacc.x[i] = __float2half_rn(acc.x[i]);
        wmma::store_matrix_sync(h2 + (size_t)(base + m * 16) * FHID + warp * 16,
                                hacc, FHID, wmma::mem_row_major);
    }
}

// ---------------- gathers (warp per destination, fp16 rows, unroll x4) -------

__device__ __forceinline__ float4 gather_node(const uint2* __restrict__ hp,
                                              int c, int lane) {
    const int beg = g_off[c], end = g_off[c + 1];
    const float dc = g_dinv[c];
    const float d2 = dc * dc;
    const float4 h = h8_to_f4(hp[(size_t)c * 32 + lane]);
    float4 acc = make_float4(h.x * d2, h.y * d2, h.z * d2, h.w * d2);
    int i = beg;
    for (; i + 4 <= end; i += 4) {
        const int2 ea = g_csr[i];
        const int2 eb = g_csr[i + 1];
        const int2 ec = g_csr[i + 2];
        const int2 ed = g_csr[i + 3];
        const float4 va = h8_to_f4(hp[(size_t)ea.x * 32 + lane]);
        const float4 vb = h8_to_f4(hp[(size_t)eb.x * 32 + lane]);
        const float4 vc = h8_to_f4(hp[(size_t)ec.x * 32 + lane]);
        const float4 vd = h8_to_f4(hp[(size_t)ed.x * 32 + lane]);
        const float na = __int_as_float(ea.y);
        const float nb = __int_as_float(eb.y);
        const float nc = __int_as_float(ec.y);
        const float nd = __int_as_float(ed.y);
        acc.x = fmaf(va.x, na, acc.x); acc.y = fmaf(va.y, na, acc.y);
        acc.z = fmaf(va.z, na, acc.z); acc.w = fmaf(va.w, na, acc.w);
        acc.x = fmaf(vb.x, nb, acc.x); acc.y = fmaf(vb.y, nb, acc.y);
        acc.z = fmaf(vb.z, nb, acc.z); acc.w = fmaf(vb.w, nb, acc.w);
        acc.x = fmaf(vc.x, nc, acc.x); acc.y = fmaf(vc.y, nc, acc.y);
        acc.z = fmaf(vc.z, nc, acc.z); acc.w = fmaf(vc.w, nc, acc.w);
        acc.x = fmaf(vd.x, nd, acc.x); acc.y = fmaf(vd.y, nd, acc.y);
        acc.z = fmaf(vd.z, nd, acc.z); acc.w = fmaf(vd.w, nd, acc.w);
    }
    for (; i < end; i++) {
        const int2 en = g_csr[i];
        const float nm = __int_as_float(en.y);
        const float4 v = h8_to_f4(hp[(size_t)en.x * 32 + lane]);
        acc.x = fmaf(v.x, nm, acc.x); acc.y = fmaf(v.y, nm, acc.y);
        acc.z = fmaf(v.z, nm, acc.z); acc.w = fmaf(v.w, nm, acc.w);
    }
    return acc;
}

// t[c] = relu(gather(h1) + b1); BN partial sums.
__global__ void k_gather1(const float* __restrict__ b1) {
    const int lane = threadIdx.x & 31;
    const int warp = (blockIdx.x * blockDim.x + threadIdx.x) >> 5;
    const int nwarps = (gridDim.x * blockDim.x) >> 5;
    const float4 bf = reinterpret_cast<const float4*>(b1)[lane];
    const uint2* hp = reinterpret_cast<const uint2*>(g_h1);
    float4* t4 = reinterpret_cast<float4*>(g_t);
    float4 s  = make_float4(0.f, 0.f, 0.f, 0.f);
    float4 ss = make_float4(0.f, 0.f, 0.f, 0.f);

    for (int c = warp; c < NNODES; c += nwarps) {
        float4 acc = gather_node(hp, c, lane);
        acc.x = fmaxf(acc.x + bf.x, 0.f);
        acc.y = fmaxf(acc.y + bf.y, 0.f);
        acc.z = fmaxf(acc.z + bf.z, 0.f);
        acc.w = fmaxf(acc.w + bf.w, 0.f);
        t4[(size_t)c * 32 + lane] = acc;
        s.x += acc.x; s.y += acc.y; s.z += acc.z; s.w += acc.w;
        ss.x += acc.x * acc.x; ss.y += acc.y * acc.y;
        ss.z += acc.z * acc.z; ss.w += acc.w * acc.w;
    }
    float* st = &g_stats[4 * lane];
    atomicAdd(st + 0, s.x); atomicAdd(st + 1, s.y);
    atomicAdd(st + 2, s.z); atomicAdd(st + 3, s.w);
    st = &g_stats[FHID + 4 * lane];
    atomicAdd(st + 0, ss.x); atomicAdd(st + 1, ss.y);
    atomicAdd(st + 2, ss.z); atomicAdd(st + 3, ss.w);
}

// out[c] = relu(gather(h2) + b2)
__global__ void k_gather2(float* __restrict__ out, const float* __restrict__ b2) {
    const int lane = threadIdx.x & 31;
    const int warp = (blockIdx.x * blockDim.x + threadIdx.x) >> 5;
    const int nwarps = (gridDim.x * blockDim.x) >> 5;
    const float4 bf = reinterpret_cast<const float4*>(b2)[lane];
    const uint2* hp = reinterpret_cast<const uint2*>(g_h2);
    float4* o4 = reinterpret_cast<float4*>(out);

    for (int c = warp; c < NNODES; c += nwarps) {
        float4 acc = gather_node(hp, c, lane);
        acc.x = fmaxf(acc.x + bf.x, 0.f);
        acc.y = fmaxf(acc.y + bf.y, 0.f);
        acc.z = fmaxf(acc.z + bf.z, 0.f);
        acc.w = fmaxf(acc.w + bf.w, 0.f);
        o4[(size_t)c * 32 + lane] = acc;
    }
}

// ---------------- launch ----------------
extern "C" void kernel_launch(void* const* d_in, const int* in_sizes, int n_in,
                              void* d_out, int out_size) {
    const float* x     = (const float*)d_in[0];
    const void*  ei    = d_in[1];                 // [2, E], int32 OR int64 (detected)
    const float* W1    = (const float*)d_in[2];
    const float* b1    = (const float*)d_in[3];
    const float* gamma = (const float*)d_in[4];
    const float* beta  = (const float*)d_in[5];
    const float* W2    = (const float*)d_in[6];
    const float* b2    = (const float*)d_in[7];
    float* out = (float*)d_out;

    k_zero_detect<<<512, 256>>>((const int*)ei, W2);
    k_deg<<<2048, 256>>>(ei);
    k_scanA<<<NB_SCAN, 256>>>();
    k_scanC<<<NB_SCAN, 256>>>();
    k_gemm1_fillcsr<<<GEMM1_BLOCKS + FILL_BLOCKS, 256>>>(x, W1, ei);
    k_gather1<<<1184, 256>>>(b1);
    k_gemm2_mma<<<MPAD / 64, 256>>>(gamma, beta);
    k_gather2<<<1184, 256>>>(out, b2);
}

// round 13
// speedup vs baseline: 1.3625x; 1.0894x over previous
#include <cuda_runtime.h>
#include <cuda_fp16.h>
#include <mma.h>
#include <stdint.h>

using namespace nvcuda;

// GCN_57501022159512: 2-layer GCN, N=100000 nodes, E=1600000 edges, 64 -> 128 -> 128.
// h1 = relu(gcnconv(x, W1, b1)); t = batchnorm(h1); out = relu(gcnconv(t, W2, b2))
//
// R13: gemm1 (inside the fused gemm1+fillcsr kernel) moved to tensor cores:
// x staged fp32->fp16 in smem, W1 pre-converted to fp16, wmma m16n16k16 with
// fp32 accum, fp16 stores into g_h1 (already fp16-staged). gemm1 was the last
// FFMA-roofline block (~30us of chip work).

#define NNODES 100000
#define NEDGES 1600000
#define FIN    64
#define FHID   128
#define BN_EPS 1e-5f

#define MPAD   100032          // NNODES rounded up to 64 (MMA M-tiles)

#define NB_SCAN 100
#define NODES_PER_BLK 1000     // NNODES / NB_SCAN, exact

#define GEMM1_BLOCKS (MPAD / 64)   // 1563 wmma tiles
#define FILL_BLOCKS  2048

// ---------------- scratch (device globals; no allocs allowed) ----------------
__device__ __half2 g_h1[MPAD * (FHID / 2)];    // x @ W1 (fp16, padded)
__device__ float   g_t [MPAD * FHID];          // gather1 output (fp32, padded)
__device__ __half2 g_h2[MPAD * (FHID / 2)];    // bn(t) @ W2 (fp16, padded)
__device__ __half  g_W1h[FIN * FHID];          // W1 in fp16 (row-major K x N)
__device__ __half  g_W2h[FHID * FHID];         // W2 in fp16 (row-major K x N)
__device__ float   g_dinv[NNODES];
__device__ int     g_deg [NNODES];
__device__ float   g_stats[2 * FHID];          // sum,sumsq
__device__ int     g_off [NNODES + 1];         // CSR offsets (by destination col)
__device__ int     g_cursor[NNODES];           // placement cursors
__device__ int2    g_csr[NEDGES];              // (src row, norm bits) sorted by dest
__device__ int     g_bsum[NB_SCAN];            // per-block degree sums
__device__ int     g_is64;

// ---------------- helpers ----------------

__device__ __forceinline__ float4 h8_to_f4(uint2 u) {
    const __half2 a = *reinterpret_cast<__half2*>(&u.x);
    const __half2 b = *reinterpret_cast<__half2*>(&u.y);
    const float2 fa = __half22float2(a);
    const float2 fb = __half22float2(b);
    return make_float4(fa.x, fa.y, fb.x, fb.y);
}

__device__ __forceinline__ int load_idx(const void* ei, int pos, bool is64) {
    int v = is64 ? (int)((const long long*)ei)[pos] : ((const int*)ei)[pos];
    return min(max(v, 0), NNODES - 1);
}

// ---------------- setup ----------------

// zero deg/stats; convert W1, W2 -> fp16; block 0 detects edge dtype.
__global__ void k_zero_detect(const int* __restrict__ w,
                              const float* __restrict__ W1,
                              const float* __restrict__ W2) {
    const int idx = blockIdx.x * blockDim.x + threadIdx.x;
    const int stride = gridDim.x * blockDim.x;
    for (int j = idx; j < NNODES; j += stride) g_deg[j] = 0;
    for (int j = idx; j < FIN * FHID; j += stride) g_W1h[j] = __float2half_rn(W1[j]);
    for (int j = idx; j < FHID * FHID; j += stride) g_W2h[j] = __float2half_rn(W2[j]);
    if (idx < 2 * FHID) g_stats[idx] = 0.f;

    if (blockIdx.x == 0) {
        __shared__ int bad;
        if (threadIdx.x == 0) bad = 0;
        __syncthreads();
        for (int j = threadIdx.x; j < 1024; j += blockDim.x) {
            const int lo = w[2 * j], hi = w[2 * j + 1];
            if (hi != 0 || lo < 0 || lo >= NNODES) bad = 1;
        }
        __syncthreads();
        if (threadIdx.x == 0) g_is64 = (bad == 0) ? 1 : 0;
    }
}

// Degree count directly from edge buffer (col half).
__global__ void k_deg(const void* __restrict__ ei) {
    const int idx = blockIdx.x * blockDim.x + threadIdx.x;
    const int stride = gridDim.x * blockDim.x;
    const bool is64 = (g_is64 != 0);
    for (int e = idx; e < NEDGES; e += stride)
        atomicAdd(&g_deg[load_idx(ei, NEDGES + e, is64)], 1);
}

// Stage A: per-block degree sums.
__global__ void k_scanA() {
    __shared__ int red[256];
    const int b = blockIdx.x;
    const int t = threadIdx.x;
    const int beg = b * NODES_PER_BLK;
    int s = 0;
    for (int i = t; i < NODES_PER_BLK; i += 256) s += g_deg[beg + i];
    red[t] = s;
    __syncthreads();
    for (int d = 128; d > 0; d >>= 1) {
        if (t < d) red[t] += red[t + d];
        __syncthreads();
    }
    if (t == 0) g_bsum[b] = red[0];
}

// Stage C: offsets + cursors + dinv (fused).
__global__ void k_scanC() {
    __shared__ int red[256];
    __shared__ int partial[256];
    __shared__ int s_base;
    const int b = blockIdx.x;
    const int t = threadIdx.x;
    const int beg = b * NODES_PER_BLK;

    int s = (t < b) ? g_bsum[t] : 0;
    red[t] = s;
    __syncthreads();
    for (int d = 128; d > 0; d >>= 1) {
        if (t < d) red[t] += red[t + d];
        __syncthreads();
    }
    if (t == 0) s_base = red[0];
    __syncthreads();

    const int cbeg = t * 4;
    int csum = 0;
    int dloc[4];
#pragma unroll
    for (int j = 0; j < 4; j++) {
        const int i = cbeg + j;
        dloc[j] = (i < NODES_PER_BLK) ? g_deg[beg + i] : 0;
        csum += dloc[j];
    }
    partial[t] = csum;
    __syncthreads();
    for (int d = 1; d < 256; d <<= 1) {
        int v = (t >= d) ? partial[t - d] : 0;
        __syncthreads();
        partial[t] += v;
        __syncthreads();
    }
    int run = s_base + ((t == 0) ? 0 : partial[t - 1]);
#pragma unroll
    for (int j = 0; j < 4; j++) {
        const int i = cbeg + j;
        if (i < NODES_PER_BLK) {
            g_off[beg + i] = run;
            g_cursor[beg + i] = run;
            g_dinv[beg + i] = rsqrtf((float)(dloc[j] + 1));
            run += dloc[j];
        }
    }
    if (b == NB_SCAN - 1 && t == 255) g_off[NNODES] = run;
}

// ---------------- fused gemm1 (wmma) + fillcsr ----------------
// Blocks [0, GEMM1_BLOCKS): one 64-row M-tile of h1 = x @ W1 on tensor cores.
// Blocks [GEMM1_BLOCKS, +FILL_BLOCKS): counting sort into g_csr.
__global__ void __launch_bounds__(256) k_gemm1_fillcsr(const float* __restrict__ x,
                                                       const void* __restrict__ ei) {
    if (blockIdx.x < GEMM1_BLOCKS) {
        __shared__ __half sA[64 * FIN];       // 8 KB
        const int t = threadIdx.x;
        const int warp = t >> 5;
        const int base = blockIdx.x * 64;

        // Stage x tile (64 x 64) fp32 -> fp16; guard tail rows.
        for (int i = t; i < 64 * FIN; i += 256) {
            const int row = base + (i >> 6);
            sA[i] = (row < NNODES) ? __float2half_rn(x[(size_t)row * FIN + (i & 63)])
                                   : __float2half_rn(0.f);
        }
        __syncthreads();

        // Preload the 4 B k-frags for this warp's 16-col N-slice.
        wmma::fragment<wmma::matrix_b, 16, 16, 16, __half, wmma::row_major> bf[4];
#pragma unroll
        for (int k = 0; k < 4; k++)
            wmma::load_matrix_sync(bf[k], g_W1h + (k * 16) * FHID + warp * 16, FHID);

        __half* h1 = reinterpret_cast<__half*>(g_h1);
#pragma unroll
        for (int m = 0; m < 4; m++) {
            wmma::fragment<wmma::accumulator, 16, 16, 16, float> acc;
            wmma::fill_fragment(acc, 0.0f);
#pragma unroll
            for (int k = 0; k < 4; k++) {
                wmma::fragment<wmma::matrix_a, 16, 16, 16, __half, wmma::row_major> af;
                wmma::load_matrix_sync(af, sA + (m * 16) * FIN + k * 16, FIN);
                wmma::mma_sync(acc, af, bf[k], acc);
            }
            wmma::fragment<wmma::accumulator, 16, 16, 16, __half> hacc;
#pragma unroll
            for (int i = 0; i < acc.num_elements; i++)
                hacc.x[i] = __float2half_rn(acc.x[i]);
            wmma::store_matrix_sync(h1 + (size_t)(base + m * 16) * FHID + warp * 16,
                                    hacc, FHID, wmma::mem_row_major);
        }
    } else {
        const int vb = blockIdx.x - GEMM1_BLOCKS;
        const int idx = vb * 256 + threadIdx.x;
        const int stride = FILL_BLOCKS * 256;
        const bool is64 = (g_is64 != 0);
        for (int e = idx; e < NEDGES; e += stride) {
            const int r = load_idx(ei, e, is64);
            const int c = load_idx(ei, NEDGES + e, is64);
            const int pos = atomicAdd(&g_cursor[c], 1);
            const float nm = g_dinv[r] * g_dinv[c];
            g_csr[pos] = make_int2(r, __float_as_int(nm));
        }
    }
}

// ---------------- GEMM2 on tensor cores (wmma fp16 / fp32 acc) ----------------
__global__ void __launch_bounds__(256) k_gemm2_mma(const float* __restrict__ gamma,
                                                   const float* __restrict__ beta) {
    __shared__ __half  sA[64 * FHID];       // 16 KB
    __shared__ float   sScale[FHID], sShift[FHID];
    const int t = threadIdx.x;
    const int warp = t >> 5;
    const int base = blockIdx.x * 64;

    if (t < FHID) {
        const float inv_n = 1.0f / (float)NNODES;
        const float mean = g_stats[t] * inv_n;
        const float var  = g_stats[FHID + t] * inv_n - mean * mean;
        const float rstd = rsqrtf(var + BN_EPS);
        const float sc = gamma[t] * rstd;
        sScale[t] = sc;
        sShift[t] = beta[t] - mean * sc;
    }
    __syncthreads();

    // Stage A: 64 x 128 fp16 with BN applied (g_t padded; padding rows are 0).
    for (int i = t; i < 64 * FHID; i += 256) {
        const int c = i & 127;
        const float v = g_t[(size_t)(base + (i >> 7)) * FHID + c];
        sA[i] = __float2half_rn(fmaf(v, sScale[c], sShift[c]));
    }
    __syncthreads();

    wmma::fragment<wmma::matrix_b, 16, 16, 16, __half, wmma::row_major> bf[8];
#pragma unroll
    for (int k = 0; k < 8; k++)
        wmma::load_matrix_sync(bf[k], g_W2h + (k * 16) * FHID + warp * 16, FHID);

    __half* h2 = reinterpret_cast<__half*>(g_h2);
#pragma unroll
    for (int m = 0; m < 4; m++) {
        wmma::fragment<wmma::accumulator, 16, 16, 16, float> acc;
        wmma::fill_fragment(acc, 0.0f);
#pragma unroll
        for (int k = 0; k < 8; k++) {
            wmma::fragment<wmma::matrix_a, 16, 16, 16, __half, wmma::row_major> af;
            wmma::load_matrix_sync(af, sA + (m * 16) * FHID + k * 16, FHID);
            wmma::mma_sync(acc, af, bf[k], acc);
        }
        wmma::fragment<wmma::accumulator, 16, 16, 16, __half> hacc;
#pragma unroll
        for (int i = 0; i < acc.num_elements; i++)
            hacc.x[i] = __float2half_rn(acc.x[i]);
        wmma::store_matrix_sync(h2 + (size_t)(base + m * 16) * FHID + warp * 16,
                                hacc, FHID, wmma::mem_row_major);
    }
}

// ---------------- gathers (warp per destination, fp16 rows, unroll x4) -------

__device__ __forceinline__ float4 gather_node(const uint2* __restrict__ hp,
                                              int c, int lane) {
    const int beg = g_off[c], end = g_off[c + 1];
    const float dc = g_dinv[c];
    const float d2 = dc * dc;
    const float4 h = h8_to_f4(hp[(size_t)c * 32 + lane]);
    float4 acc = make_float4(h.x * d2, h.y * d2, h.z * d2, h.w * d2);
    int i = beg;
    for (; i + 4 <= end; i += 4) {
        const int2 ea = g_csr[i];
        const int2 eb = g_csr[i + 1];
        const int2 ec = g_csr[i + 2];
        const int2 ed = g_csr[i + 3];
        const float4 va = h8_to_f4(hp[(size_t)ea.x * 32 + lane]);
        const float4 vb = h8_to_f4(hp[(size_t)eb.x * 32 + lane]);
        const float4 vc = h8_to_f4(hp[(size_t)ec.x * 32 + lane]);
        const float4 vd = h8_to_f4(hp[(size_t)ed.x * 32 + lane]);
        const float na = __int_as_float(ea.y);
        const float nb = __int_as_float(eb.y);
        const float nc = __int_as_float(ec.y);
        const float nd = __int_as_float(ed.y);
        acc.x = fmaf(va.x, na, acc.x); acc.y = fmaf(va.y, na, acc.y);
        acc.z = fmaf(va.z, na, acc.z); acc.w = fmaf(va.w, na, acc.w);
        acc.x = fmaf(vb.x, nb, acc.x); acc.y = fmaf(vb.y, nb, acc.y);
        acc.z = fmaf(vb.z, nb, acc.z); acc.w = fmaf(vb.w, nb, acc.w);
        acc.x = fmaf(vc.x, nc, acc.x); acc.y = fmaf(vc.y, nc, acc.y);
        acc.z = fmaf(vc.z, nc, acc.z); acc.w = fmaf(vc.w, nc, acc.w);
        acc.x = fmaf(vd.x, nd, acc.x); acc.y = fmaf(vd.y, nd, acc.y);
        acc.z = fmaf(vd.z, nd, acc.z); acc.w = fmaf(vd.w, nd, acc.w);
    }
    for (; i < end; i++) {
        const int2 en = g_csr[i];
        const float nm = __int_as_float(en.y);
        const float4 v = h8_to_f4(hp[(size_t)en.x * 32 + lane]);
        acc.x = fmaf(v.x, nm, acc.x); acc.y = fmaf(v.y, nm, acc.y);
        acc.z = fmaf(v.z, nm, acc.z); acc.w = fmaf(v.w, nm, acc.w);
    }
    return acc;
}

// t[c] = relu(gather(h1) + b1); BN partial sums.
__global__ void k_gather1(const float* __restrict__ b1) {
    const int lane = threadIdx.x & 31;
    const int warp = (blockIdx.x * blockDim.x + threadIdx.x) >> 5;
    const int nwarps = (gridDim.x * blockDim.x) >> 5;
    const float4 bf = reinterpret_cast<const float4*>(b1)[lane];
    const uint2* hp = reinterpret_cast<const uint2*>(g_h1);
    float4* t4 = reinterpret_cast<float4*>(g_t);
    float4 s  = make_float4(0.f, 0.f, 0.f, 0.f);
    float4 ss = make_float4(0.f, 0.f, 0.f, 0.f);

    for (int c = warp; c < NNODES; c += nwarps) {
        float4 acc = gather_node(hp, c, lane);
        acc.x = fmaxf(acc.x + bf.x, 0.f);
        acc.y = fmaxf(acc.y + bf.y, 0.f);
        acc.z = fmaxf(acc.z + bf.z, 0.f);
        acc.w = fmaxf(acc.w + bf.w, 0.f);
        t4[(size_t)c * 32 + lane] = acc;
        s.x += acc.x; s.y += acc.y; s.z += acc.z; s.w += acc.w;
        ss.x += acc.x * acc.x; ss.y += acc.y * acc.y;
        ss.z += acc.z * acc.z; ss.w += acc.w * acc.w;
    }
    float* st = &g_stats[4 * lane];
    atomicAdd(st + 0, s.x); atomicAdd(st + 1, s.y);
    atomicAdd(st + 2, s.z); atomicAdd(st + 3, s.w);
    st = &g_stats[FHID + 4 * lane];
    atomicAdd(st + 0, ss.x); atomicAdd(st + 1, ss.y);
    atomicAdd(st + 2, ss.z); atomicAdd(st + 3, ss.w);
}

// out[c] = relu(gather(h2) + b2)
__global__ void k_gather2(float* __restrict__ out, const float* __restrict__ b2) {
    const int lane = threadIdx.x & 31;
    const int warp = (blockIdx.x * blockDim.x + threadIdx.x) >> 5;
    const int nwarps = (gridDim.x * blockDim.x) >> 5;
    const float4 bf = reinterpret_cast<const float4*>(b2)[lane];
    const uint2* hp = reinterpret_cast<const uint2*>(g_h2);
    float4* o4 = reinterpret_cast<float4*>(out);

    for (int c = warp; c < NNODES; c += nwarps) {
        float4 acc = gather_node(hp, c, lane);
        acc.x = fmaxf(acc.x + bf.x, 0.f);
        acc.y = fmaxf(acc.y + bf.y, 0.f);
        acc.z = fmaxf(acc.z + bf.z, 0.f);
        acc.w = fmaxf(acc.w + bf.w, 0.f);
        o4[(size_t)c * 32 + lane] = acc;
    }
}

// ---------------- launch ----------------
extern "C" void kernel_launch(void* const* d_in, const int* in_sizes, int n_in,
                              void* d_out, int out_size) {
    const float* x     = (const float*)d_in[0];
    const void*  ei    = d_in[1];                 // [2, E], int32 OR int64 (detected)
    const float* W1    = (const float*)d_in[2];
    const float* b1    = (const float*)d_in[3];
    const float* gamma = (const float*)d_in[4];
    const float* beta  = (const float*)d_in[5];
    const float* W2    = (const float*)d_in[6];
    const float* b2    = (const float*)d_in[7];
    float* out = (float*)d_out;

    k_zero_detect<<<512, 256>>>((const int*)ei, W1, W2);
    k_deg<<<2048, 256>>>(ei);
    k_scanA<<<NB_SCAN, 256>>>();
    k_scanC<<<NB_SCAN, 256>>>();
    k_gemm1_fillcsr<<<GEMM1_BLOCKS + FILL_BLOCKS, 256>>>(x, ei);
    k_gather1<<<1184, 256>>>(b1);
    k_gemm2_mma<<<MPAD / 64, 256>>>(gamma, beta);
    k_gather2<<<1184, 256>>>(out, b2);
}

// round 14
// speedup vs baseline: 2.1217x; 1.5572x over previous
#include <cuda_runtime.h>
#include <cuda_fp16.h>
#include <mma.h>
#include <stdint.h>

using namespace nvcuda;

// GCN_57501022159512: 2-layer GCN, N=100000 nodes, E=1600000 edges, 64 -> 128 -> 128.
// h1 = relu(gcnconv(x, W1, b1)); t = batchnorm(h1); out = relu(gcnconv(t, W2, b2))
//
// R14: (1) gathers use 16-lane virtual warps with uint4 (128-bit) row loads —
// 2x node parallelism, half the LDG issues. (2) gather1 BN stats reduced in
// shared memory per block (was 2.4M global atomics on 256 addresses).
// (3) k_deg fused with gemm1-wmma; fillcsr standalone after scan.

#define NNODES 100000
#define NEDGES 1600000
#define FIN    64
#define FHID   128
#define BN_EPS 1e-5f

#define MPAD   100032          // NNODES rounded up to 64 (MMA M-tiles)

#define NB_SCAN 100
#define NODES_PER_BLK 1000     // NNODES / NB_SCAN, exact

#define GEMM1_BLOCKS (MPAD / 64)   // 1563 wmma tiles
#define DEG_BLOCKS   2048
#define FILL_BLOCKS  2048

// ---------------- scratch (device globals; no allocs allowed) ----------------
__device__ __half2 g_h1[MPAD * (FHID / 2)];    // x @ W1 (fp16, padded)
__device__ float   g_t [MPAD * FHID];          // gather1 output (fp32, padded)
__device__ __half2 g_h2[MPAD * (FHID / 2)];    // bn(t) @ W2 (fp16, padded)
__device__ __half  g_W1h[FIN * FHID];          // W1 in fp16 (row-major K x N)
__device__ __half  g_W2h[FHID * FHID];         // W2 in fp16 (row-major K x N)
__device__ float   g_dinv[NNODES];
__device__ int     g_deg [NNODES];
__device__ float   g_stats[2 * FHID];          // sum,sumsq
__device__ int     g_off [NNODES + 1];         // CSR offsets (by destination col)
__device__ int     g_cursor[NNODES];           // placement cursors
__device__ int2    g_csr[NEDGES];              // (src row, norm bits) sorted by dest
__device__ int     g_bsum[NB_SCAN];            // per-block degree sums
__device__ int     g_is64;

// ---------------- helpers ----------------

__device__ __forceinline__ void h16_to_f8(uint4 u, float4& a, float4& b) {
    const float2 f0 = __half22float2(*reinterpret_cast<__half2*>(&u.x));
    const float2 f1 = __half22float2(*reinterpret_cast<__half2*>(&u.y));
    const float2 f2 = __half22float2(*reinterpret_cast<__half2*>(&u.z));
    const float2 f3 = __half22float2(*reinterpret_cast<__half2*>(&u.w));
    a = make_float4(f0.x, f0.y, f1.x, f1.y);
    b = make_float4(f2.x, f2.y, f3.x, f3.y);
}

__device__ __forceinline__ void fma8(float4& a0, float4& a1, uint4 u, float nm) {
    float4 v0, v1;
    h16_to_f8(u, v0, v1);
    a0.x = fmaf(v0.x, nm, a0.x); a0.y = fmaf(v0.y, nm, a0.y);
    a0.z = fmaf(v0.z, nm, a0.z); a0.w = fmaf(v0.w, nm, a0.w);
    a1.x = fmaf(v1.x, nm, a1.x); a1.y = fmaf(v1.y, nm, a1.y);
    a1.z = fmaf(v1.z, nm, a1.z); a1.w = fmaf(v1.w, nm, a1.w);
}

__device__ __forceinline__ int load_idx(const void* ei, int pos, bool is64) {
    int v = is64 ? (int)((const long long*)ei)[pos] : ((const int*)ei)[pos];
    return min(max(v, 0), NNODES - 1);
}

// ---------------- setup ----------------

// zero deg/stats; convert W1, W2 -> fp16; block 0 detects edge dtype.
__global__ void k_zero_detect(const int* __restrict__ w,
                              const float* __restrict__ W1,
                              const float* __restrict__ W2) {
    const int idx = blockIdx.x * blockDim.x + threadIdx.x;
    const int stride = gridDim.x * blockDim.x;
    for (int j = idx; j < NNODES; j += stride) g_deg[j] = 0;
    for (int j = idx; j < FIN * FHID; j += stride) g_W1h[j] = __float2half_rn(W1[j]);
    for (int j = idx; j < FHID * FHID; j += stride) g_W2h[j] = __float2half_rn(W2[j]);
    if (idx < 2 * FHID) g_stats[idx] = 0.f;

    if (blockIdx.x == 0) {
        __shared__ int bad;
        if (threadIdx.x == 0) bad = 0;
        __syncthreads();
        for (int j = threadIdx.x; j < 1024; j += blockDim.x) {
            const int lo = w[2 * j], hi = w[2 * j + 1];
            if (hi != 0 || lo < 0 || lo >= NNODES) bad = 1;
        }
        __syncthreads();
        if (threadIdx.x == 0) g_is64 = (bad == 0) ? 1 : 0;
    }
}

// ---------------- fused gemm1 (wmma) + degree count ----------------
__global__ void __launch_bounds__(256) k_deg_gemm1(const float* __restrict__ x,
                                                   const void* __restrict__ ei) {
    if (blockIdx.x < GEMM1_BLOCKS) {
        __shared__ __half sA[64 * FIN];       // 8 KB
        const int t = threadIdx.x;
        const int warp = t >> 5;
        const int base = blockIdx.x * 64;

        for (int i = t; i < 64 * FIN; i += 256) {
            const int row = base + (i >> 6);
            sA[i] = (row < NNODES) ? __float2half_rn(x[(size_t)row * FIN + (i & 63)])
                                   : __float2half_rn(0.f);
        }
        __syncthreads();

        wmma::fragment<wmma::matrix_b, 16, 16, 16, __half, wmma::row_major> bf[4];
#pragma unroll
        for (int k = 0; k < 4; k++)
            wmma::load_matrix_sync(bf[k], g_W1h + (k * 16) * FHID + warp * 16, FHID);

        __half* h1 = reinterpret_cast<__half*>(g_h1);
#pragma unroll
        for (int m = 0; m < 4; m++) {
            wmma::fragment<wmma::accumulator, 16, 16, 16, float> acc;
            wmma::fill_fragment(acc, 0.0f);
#pragma unroll
            for (int k = 0; k < 4; k++) {
                wmma::fragment<wmma::matrix_a, 16, 16, 16, __half, wmma::row_major> af;
                wmma::load_matrix_sync(af, sA + (m * 16) * FIN + k * 16, FIN);
                wmma::mma_sync(acc, af, bf[k], acc);
            }
            wmma::fragment<wmma::accumulator, 16, 16, 16, __half> hacc;
#pragma unroll
            for (int i = 0; i < acc.num_elements; i++)
                hacc.x[i] = __float2half_rn(acc.x[i]);
            wmma::store_matrix_sync(h1 + (size_t)(base + m * 16) * FHID + warp * 16,
                                    hacc, FHID, wmma::mem_row_major);
        }
    } else {
        const int vb = blockIdx.x - GEMM1_BLOCKS;
        const int idx = vb * 256 + threadIdx.x;
        const int stride = DEG_BLOCKS * 256;
        const bool is64 = (g_is64 != 0);
        for (int e = idx; e < NEDGES; e += stride)
            atomicAdd(&g_deg[load_idx(ei, NEDGES + e, is64)], 1);
    }
}

// Stage A: per-block degree sums.
__global__ void k_scanA() {
    __shared__ int red[256];
    const int b = blockIdx.x;
    const int t = threadIdx.x;
    const int beg = b * NODES_PER_BLK;
    int s = 0;
    for (int i = t; i < NODES_PER_BLK; i += 256) s += g_deg[beg + i];
    red[t] = s;
    __syncthreads();
    for (int d = 128; d > 0; d >>= 1) {
        if (t < d) red[t] += red[t + d];
        __syncthreads();
    }
    if (t == 0) g_bsum[b] = red[0];
}

// Stage C: offsets + cursors + dinv (fused).
__global__ void k_scanC() {
    __shared__ int red[256];
    __shared__ int partial[256];
    __shared__ int s_base;
    const int b = blockIdx.x;
    const int t = threadIdx.x;
    const int beg = b * NODES_PER_BLK;

    int s = (t < b) ? g_bsum[t] : 0;
    red[t] = s;
    __syncthreads();
    for (int d = 128; d > 0; d >>= 1) {
        if (t < d) red[t] += red[t + d];
        __syncthreads();
    }
    if (t == 0) s_base = red[0];
    __syncthreads();

    const int cbeg = t * 4;
    int csum = 0;
    int dloc[4];
#pragma unroll
    for (int j = 0; j < 4; j++) {
        const int i = cbeg + j;
        dloc[j] = (i < NODES_PER_BLK) ? g_deg[beg + i] : 0;
        csum += dloc[j];
    }
    partial[t] = csum;
    __syncthreads();
    for (int d = 1; d < 256; d <<= 1) {
        int v = (t >= d) ? partial[t - d] : 0;
        __syncthreads();
        partial[t] += v;
        __syncthreads();
    }
    int run = s_base + ((t == 0) ? 0 : partial[t - 1]);
#pragma unroll
    for (int j = 0; j < 4; j++) {
        const int i = cbeg + j;
        if (i < NODES_PER_BLK) {
            g_off[beg + i] = run;
            g_cursor[beg + i] = run;
            g_dinv[beg + i] = rsqrtf((float)(dloc[j] + 1));
            run += dloc[j];
        }
    }
    if (b == NB_SCAN - 1 && t == 255) g_off[NNODES] = run;
}

// Counting sort directly from edge buffer.
__global__ void k_fillcsr(const void* __restrict__ ei) {
    const int idx = blockIdx.x * blockDim.x + threadIdx.x;
    const int stride = gridDim.x * blockDim.x;
    const bool is64 = (g_is64 != 0);
    for (int e = idx; e < NEDGES; e += stride) {
        const int r = load_idx(ei, e, is64);
        const int c = load_idx(ei, NEDGES + e, is64);
        const int pos = atomicAdd(&g_cursor[c], 1);
        const float nm = g_dinv[r] * g_dinv[c];
        g_csr[pos] = make_int2(r, __float_as_int(nm));
    }
}

// ---------------- GEMM2 on tensor cores (wmma fp16 / fp32 acc) ----------------
__global__ void __launch_bounds__(256) k_gemm2_mma(const float* __restrict__ gamma,
                                                   const float* __restrict__ beta) {
    __shared__ __half  sA[64 * FHID];       // 16 KB
    __shared__ float   sScale[FHID], sShift[FHID];
    const int t = threadIdx.x;
    const int warp = t >> 5;
    const int base = blockIdx.x * 64;

    if (t < FHID) {
        const float inv_n = 1.0f / (float)NNODES;
        const float mean = g_stats[t] * inv_n;
        const float var  = g_stats[FHID + t] * inv_n - mean * mean;
        const float rstd = rsqrtf(var + BN_EPS);
        const float sc = gamma[t] * rstd;
        sScale[t] = sc;
        sShift[t] = beta[t] - mean * sc;
    }
    __syncthreads();

    for (int i = t; i < 64 * FHID; i += 256) {
        const int c = i & 127;
        const float v = g_t[(size_t)(base + (i >> 7)) * FHID + c];
        sA[i] = __float2half_rn(fmaf(v, sScale[c], sShift[c]));
    }
    __syncthreads();

    wmma::fragment<wmma::matrix_b, 16, 16, 16, __half, wmma::row_major> bf[8];
#pragma unroll
    for (int k = 0; k < 8; k++)
        wmma::load_matrix_sync(bf[k], g_W2h + (k * 16) * FHID + warp * 16, FHID);

    __half* h2 = reinterpret_cast<__half*>(g_h2);
#pragma unroll
    for (int m = 0; m < 4; m++) {
        wmma::fragment<wmma::accumulator, 16, 16, 16, float> acc;
        wmma::fill_fragment(acc, 0.0f);
#pragma unroll
        for (int k = 0; k < 8; k++) {
            wmma::fragment<wmma::matrix_a, 16, 16, 16, __half, wmma::row_major> af;
            wmma::load_matrix_sync(af, sA + (m * 16) * FHID + k * 16, FHID);
            wmma::mma_sync(acc, af, bf[k], acc);
        }
        wmma::fragment<wmma::accumulator, 16, 16, 16, __half> hacc;
#pragma unroll
        for (int i = 0; i < acc.num_elements; i++)
            hacc.x[i] = __float2half_rn(acc.x[i]);
        wmma::store_matrix_sync(h2 + (size_t)(base + m * 16) * FHID + warp * 16,
                                hacc, FHID, wmma::mem_row_major);
    }
}

// ---------------- gathers: 16-lane virtual warps, uint4 rows, unroll x4 ------

// Computes acc (8 features per lane) for node c from fp16 matrix hp.
__device__ __forceinline__ void gather_node16(const uint4* __restrict__ hp,
                                              int c, int lane,
                                              float4& acc0, float4& acc1) {
    const int beg = g_off[c], end = g_off[c + 1];
    const float dc = g_dinv[c];
    const float d2 = dc * dc;
    float4 h0, h1;
    h16_to_f8(hp[(size_t)c * 16 + lane], h0, h1);
    acc0 = make_float4(h0.x * d2, h0.y * d2, h0.z * d2, h0.w * d2);
    acc1 = make_float4(h1.x * d2, h1.y * d2, h1.z * d2, h1.w * d2);
    int i = beg;
    for (; i + 4 <= end; i += 4) {
        const int2 e0 = g_csr[i];
        const int2 e1 = g_csr[i + 1];
        const int2 e2 = g_csr[i + 2];
        const int2 e3 = g_csr[i + 3];
        const uint4 u0 = hp[(size_t)e0.x * 16 + lane];
        const uint4 u1 = hp[(size_t)e1.x * 16 + lane];
        const uint4 u2 = hp[(size_t)e2.x * 16 + lane];
        const uint4 u3 = hp[(size_t)e3.x * 16 + lane];
        fma8(acc0, acc1, u0, __int_as_float(e0.y));
        fma8(acc0, acc1, u1, __int_as_float(e1.y));
        fma8(acc0, acc1, u2, __int_as_float(e2.y));
        fma8(acc0, acc1, u3, __int_as_float(e3.y));
    }
    for (; i < end; i++) {
        const int2 en = g_csr[i];
        fma8(acc0, acc1, hp[(size_t)en.x * 16 + lane], __int_as_float(en.y));
    }
}

// t[c] = relu(gather(h1) + b1); BN partial sums (block-level smem reduction).
__global__ void __launch_bounds__(256) k_gather1(const float* __restrict__ b1) {
    __shared__ float ssum[2 * FHID];
    const int lane = threadIdx.x & 15;
    const int vw   = (blockIdx.x * blockDim.x + threadIdx.x) >> 4;
    const int nvw  = (gridDim.x * blockDim.x) >> 4;
    const float4 bf0 = reinterpret_cast<const float4*>(b1)[2 * lane];
    const float4 bf1 = reinterpret_cast<const float4*>(b1)[2 * lane + 1];
    const uint4* hp = reinterpret_cast<const uint4*>(g_h1);
    float4* t4 = reinterpret_cast<float4*>(g_t);

    for (int i = threadIdx.x; i < 2 * FHID; i += 256) ssum[i] = 0.f;
    __syncthreads();

    float4 s0  = make_float4(0.f, 0.f, 0.f, 0.f), s1  = s0;
    float4 ss0 = s0, ss1 = s0;

    for (int c = vw; c < NNODES; c += nvw) {
        float4 a0, a1;
        gather_node16(hp, c, lane, a0, a1);
        a0.x = fmaxf(a0.x + bf0.x, 0.f); a0.y = fmaxf(a0.y + bf0.y, 0.f);
        a0.z = fmaxf(a0.z + bf0.z, 0.f); a0.w = fmaxf(a0.w + bf0.w, 0.f);
        a1.x = fmaxf(a1.x + bf1.x, 0.f); a1.y = fmaxf(a1.y + bf1.y, 0.f);
        a1.z = fmaxf(a1.z + bf1.z, 0.f); a1.w = fmaxf(a1.w + bf1.w, 0.f);
        t4[(size_t)c * 32 + 2 * lane]     = a0;
        t4[(size_t)c * 32 + 2 * lane + 1] = a1;
        s0.x += a0.x; s0.y += a0.y; s0.z += a0.z; s0.w += a0.w;
        s1.x += a1.x; s1.y += a1.y; s1.z += a1.z; s1.w += a1.w;
        ss0.x += a0.x * a0.x; ss0.y += a0.y * a0.y;
        ss0.z += a0.z * a0.z; ss0.w += a0.w * a0.w;
        ss1.x += a1.x * a1.x; ss1.y += a1.y * a1.y;
        ss1.z += a1.z * a1.z; ss1.w += a1.w * a1.w;
    }

    const int fb = 8 * lane;
    atomicAdd(&ssum[fb + 0], s0.x); atomicAdd(&ssum[fb + 1], s0.y);
    atomicAdd(&ssum[fb + 2], s0.z); atomicAdd(&ssum[fb + 3], s0.w);
    atomicAdd(&ssum[fb + 4], s1.x); atomicAdd(&ssum[fb + 5], s1.y);
    atomicAdd(&ssum[fb + 6], s1.z); atomicAdd(&ssum[fb + 7], s1.w);
    atomicAdd(&ssum[FHID + fb + 0], ss0.x); atomicAdd(&ssum[FHID + fb + 1], ss0.y);
    atomicAdd(&ssum[FHID + fb + 2], ss0.z); atomicAdd(&ssum[FHID + fb + 3], ss0.w);
    atomicAdd(&ssum[FHID + fb + 4], ss1.x); atomicAdd(&ssum[FHID + fb + 5], ss1.y);
    atomicAdd(&ssum[FHID + fb + 6], ss1.z); atomicAdd(&ssum[FHID + fb + 7], ss1.w);
    __syncthreads();
    for (int i = threadIdx.x; i < 2 * FHID; i += 256)
        atomicAdd(&g_stats[i], ssum[i]);
}

// out[c] = relu(gather(h2) + b2)
__global__ void __launch_bounds__(256) k_gather2(float* __restrict__ out,
                                                 const float* __restrict__ b2) {
    const int lane = threadIdx.x & 15;
    const int vw   = (blockIdx.x * blockDim.x + threadIdx.x) >> 4;
    const int nvw  = (gridDim.x * blockDim.x) >> 4;
    const float4 bf0 = reinterpret_cast<const float4*>(b2)[2 * lane];
    const float4 bf1 = reinterpret_cast<const float4*>(b2)[2 * lane + 1];
    const uint4* hp = reinterpret_cast<const uint4*>(g_h2);
    float4* o4 = reinterpret_cast<float4*>(out);

    for (int c = vw; c < NNODES; c += nvw) {
        float4 a0, a1;
        gather_node16(hp, c, lane, a0, a1);
        a0.x = fmaxf(a0.x + bf0.x, 0.f); a0.y = fmaxf(a0.y + bf0.y, 0.f);
        a0.z = fmaxf(a0.z + bf0.z, 0.f); a0.w = fmaxf(a0.w + bf0.w, 0.f);
        a1.x = fmaxf(a1.x + bf1.x, 0.f); a1.y = fmaxf(a1.y + bf1.y, 0.f);
        a1.z = fmaxf(a1.z + bf1.z, 0.f); a1.w = fmaxf(a1.w + bf1.w, 0.f);
        o4[(size_t)c * 32 + 2 * lane]     = a0;
        o4[(size_t)c * 32 + 2 * lane + 1] = a1;
    }
}

// ---------------- launch ----------------
extern "C" void kernel_launch(void* const* d_in, const int* in_sizes, int n_in,
                              void* d_out, int out_size) {
    const float* x     = (const float*)d_in[0];
    const void*  ei    = d_in[1];                 // [2, E], int32 OR int64 (detected)
    const float* W1    = (const float*)d_in[2];
    const float* b1    = (const float*)d_in[3];
    const float* gamma = (const float*)d_in[4];
    const float* beta  = (const float*)d_in[5];
    const float* W2    = (const float*)d_in[6];
    const float* b2    = (const float*)d_in[7];
    float* out = (float*)d_out;

    k_zero_detect<<<512, 256>>>((const int*)ei, W1, W2);
    k_deg_gemm1<<<GEMM1_BLOCKS + DEG_BLOCKS, 256>>>(x, ei);
    k_scanA<<<NB_SCAN, 256>>>();
    k_scanC<<<NB_SCAN, 256>>>();
    k_fillcsr<<<FILL_BLOCKS, 256>>>(ei);
    k_gather1<<<1184, 256>>>(b1);
    k_gemm2_mma<<<MPAD / 64, 256>>>(gamma, beta);
    k_gather2<<<1184, 256>>>(out, b2);
}